// round 2
// baseline (speedup 1.0000x reference)
#include <cuda_runtime.h>
#include <math.h>

#define Mdim 256
#define Ldim 4096
#define Tdim 2048

static const float kRIDGE = 0.01f;
#define LOG2E_F 1.4426950408889634f

// ---------------- device scratch (no allocations allowed) ----------------
__device__ float g_Rre[Mdim*Mdim], g_Rim[Mdim*Mdim];
__device__ float g_Gre[Mdim*Mdim], g_Gim[Mdim*Mdim];
__device__ float g_Xa_re[Mdim*Mdim], g_Xa_im[Mdim*Mdim];
__device__ float g_Xb_re[Mdim*Mdim], g_Xb_im[Mdim*Mdim];
__device__ float g_P_re[Mdim*Mdim], g_P_im[Mdim*Mdim];
__device__ float g_part_re[16*Mdim*Mdim], g_part_im[16*Mdim*Mdim];
__device__ float g_Zre[Mdim*Ldim], g_Zim[Mdim*Ldim];
__device__ float g_GZre[Mdim*Ldim], g_GZim[Mdim*Ldim];
__device__ float g_v[Ldim], g_u[Ldim], g_up[Ldim], g_attn[Ldim];
__device__ float g_scal[4];   // [0]=row-norm bound, [1]=kv2min, [2]=kv2max

__device__ __forceinline__ float warp_sum(float v) {
    #pragma unroll
    for (int o = 16; o > 0; o >>= 1) v += __shfl_xor_sync(0xffffffffu, v, o);
    return v;
}

// ---------------- init ----------------
__global__ void init_scal_kernel() {
    g_scal[0] = 0.f; g_scal[1] = 0.f; g_scal[2] = 0.f; g_scal[3] = 0.f;
}

// ---------------- C = (A*diag(w)) @ A^H  (partial over k-split) ----------------
// Output tile (64x64), K chunked via blockIdx.z. A is [256 x K] planar (re/im).
__global__ __launch_bounds__(256)
void csyrk_part(float* __restrict__ Pre, float* __restrict__ Pim,
                const float* __restrict__ Are, const float* __restrict__ Aim,
                const float* __restrict__ w, int lda, int kChunk)
{
    const int BM = 64, BN = 64, BK = 32, TM = 4, TN = 4;
    __shared__ float as_re[BK][BM+1], as_im[BK][BM+1];
    __shared__ float bs_re[BK][BN+1], bs_im[BK][BN+1];
    int i0 = blockIdx.y * BM, j0 = blockIdx.x * BN;
    int k0 = blockIdx.z * kChunk;
    int t  = threadIdx.x;
    int tx = t & 15, ty = t >> 4;
    float cre[TM][TN] = {}, cim[TM][TN] = {};

    for (int kb = 0; kb < kChunk; kb += BK) {
        #pragma unroll
        for (int e = t; e < BM*BK; e += 256) {
            int row = e >> 5, kk = e & 31;
            int g = (i0 + row) * lda + k0 + kb + kk;
            float ww = w ? w[k0 + kb + kk] : 1.0f;
            as_re[kk][row] = Are[g] * ww;
            as_im[kk][row] = Aim[g] * ww;
        }
        #pragma unroll
        for (int e = t; e < BN*BK; e += 256) {
            int col = e >> 5, kk = e & 31;
            int g = (j0 + col) * lda + k0 + kb + kk;
            bs_re[kk][col] = Are[g];
            bs_im[kk][col] = Aim[g];
        }
        __syncthreads();
        #pragma unroll 4
        for (int kk = 0; kk < BK; kk++) {
            float ar[TM], ai[TM], br[TN], bi[TN];
            #pragma unroll
            for (int i = 0; i < TM; i++) { ar[i] = as_re[kk][ty*TM+i]; ai[i] = as_im[kk][ty*TM+i]; }
            #pragma unroll
            for (int j = 0; j < TN; j++) { br[j] = bs_re[kk][tx*TN+j]; bi[j] = bs_im[kk][tx*TN+j]; }
            #pragma unroll
            for (int i = 0; i < TM; i++)
                #pragma unroll
                for (int j = 0; j < TN; j++) {
                    // a * conj(b)
                    cre[i][j] += ar[i]*br[j];
                    cre[i][j] += ai[i]*bi[j];
                    cim[i][j] += ai[i]*br[j];
                    cim[i][j] -= ar[i]*bi[j];
                }
        }
        __syncthreads();
    }
    size_t off = (size_t)blockIdx.z * (Mdim * Mdim);
    #pragma unroll
    for (int i = 0; i < TM; i++)
        #pragma unroll
        for (int j = 0; j < TN; j++) {
            int gi = i0 + ty*TM + i, gj = j0 + tx*TN + j;
            Pre[off + gi*Mdim + gj] = cre[i][j];
            Pim[off + gi*Mdim + gj] = cim[i][j];
        }
}

// sum k-split partials, optionally add ridge on diagonal
__global__ void reduce_RG(float* __restrict__ Cre, float* __restrict__ Cim,
                          int SK, int addRidge)
{
    int e = blockIdx.x * 256 + threadIdx.x;
    float sr = 0.f, si = 0.f;
    for (int z = 0; z < SK; z++) { sr += g_part_re[z*Mdim*Mdim + e]; si += g_part_im[z*Mdim*Mdim + e]; }
    if (addRidge && (e >> 8) == (e & 255)) sr += kRIDGE;
    Cre[e] = sr; Cim[e] = si;
}

// ---------------- Gershgorin bound: max row abs-sum of R ----------------
__global__ void rownorm_kernel() {
    int warp = threadIdx.x >> 5, lane = threadIdx.x & 31;
    int i = blockIdx.x * 8 + warp;
    float s = 0.f;
    for (int j = lane; j < Mdim; j += 32)
        s += fabsf(g_Rre[i*Mdim + j]) + fabsf(g_Rim[i*Mdim + j]);
    s = warp_sum(s);
    if (lane == 0) atomicMax((unsigned int*)&g_scal[0], __float_as_uint(s));
}

__global__ void init_X0(float* __restrict__ Xre, float* __restrict__ Xim) {
    int i = blockIdx.x, j = threadIdx.x;
    float inv = 1.0f / g_scal[0];
    Xre[i*Mdim + j] = (i == j) ? inv : 0.f;
    Xim[i*Mdim + j] = 0.f;
}

// ---------------- generic complex NN GEMM (planar), k-split partials ----------------
template<int BM, int BN, int BK, int TM, int TN>
__global__ __launch_bounds__(256)
void cgemm_nn(float* __restrict__ Cre, float* __restrict__ Cim,
              const float* __restrict__ Are, const float* __restrict__ Aim, int lda,
              const float* __restrict__ Bre, const float* __restrict__ Bim, int ldb,
              int kChunk, int MNpart)
{
    __shared__ float as_re[BK][BM+1], as_im[BK][BM+1];
    __shared__ float bs_re[BK][BN+1], bs_im[BK][BN+1];
    int i0 = blockIdx.y * BM, j0 = blockIdx.x * BN;
    int k0 = blockIdx.z * kChunk;
    int t  = threadIdx.x;
    int tx = t % (BN/TN), ty = t / (BN/TN);
    float cre[TM][TN] = {}, cim[TM][TN] = {};

    for (int kb = 0; kb < kChunk; kb += BK) {
        #pragma unroll
        for (int e = t; e < BM*BK; e += 256) {
            int row = e / BK, kk = e % BK;
            int g = (i0 + row) * lda + k0 + kb + kk;
            as_re[kk][row] = Are[g];
            as_im[kk][row] = Aim[g];
        }
        #pragma unroll
        for (int e = t; e < BK*BN; e += 256) {
            int kk = e / BN, col = e % BN;
            int g = (k0 + kb + kk) * ldb + j0 + col;
            bs_re[kk][col] = Bre[g];
            bs_im[kk][col] = Bim[g];
        }
        __syncthreads();
        #pragma unroll 4
        for (int kk = 0; kk < BK; kk++) {
            float ar[TM], ai[TM], br[TN], bi[TN];
            #pragma unroll
            for (int i = 0; i < TM; i++) { ar[i] = as_re[kk][ty*TM+i]; ai[i] = as_im[kk][ty*TM+i]; }
            #pragma unroll
            for (int j = 0; j < TN; j++) { br[j] = bs_re[kk][tx*TN+j]; bi[j] = bs_im[kk][tx*TN+j]; }
            #pragma unroll
            for (int i = 0; i < TM; i++)
                #pragma unroll
                for (int j = 0; j < TN; j++) {
                    cre[i][j] += ar[i]*br[j];
                    cre[i][j] -= ai[i]*bi[j];
                    cim[i][j] += ar[i]*bi[j];
                    cim[i][j] += ai[i]*br[j];
                }
        }
        __syncthreads();
    }
    size_t off = (size_t)blockIdx.z * MNpart;
    #pragma unroll
    for (int i = 0; i < TM; i++)
        #pragma unroll
        for (int j = 0; j < TN; j++) {
            int gi = i0 + ty*TM + i, gj = j0 + tx*TN + j;
            Cre[off + (size_t)gi*ldb + gj] = cre[i][j];
            Cim[off + (size_t)gi*ldb + gj] = cim[i][j];
        }
}

__global__ void reduce_sum(float* __restrict__ Cre, float* __restrict__ Cim, int SK) {
    int e = blockIdx.x * 256 + threadIdx.x;
    float sr = 0.f, si = 0.f;
    for (int z = 0; z < SK; z++) { sr += g_part_re[z*Mdim*Mdim + e]; si += g_part_im[z*Mdim*Mdim + e]; }
    Cre[e] = sr; Cim[e] = si;
}

// Xn = 2*X - sum_z part[z]
__global__ void reduce_newton(float* __restrict__ Xnre, float* __restrict__ Xnim,
                              const float* __restrict__ Xre, const float* __restrict__ Xim, int SK)
{
    int e = blockIdx.x * 256 + threadIdx.x;
    float sr = 0.f, si = 0.f;
    for (int z = 0; z < SK; z++) { sr += g_part_re[z*Mdim*Mdim + e]; si += g_part_im[z*Mdim*Mdim + e]; }
    Xnre[e] = 2.f*Xre[e] - sr;
    Xnim[e] = 2.f*Xim[e] - si;
}

// ---------------- q, d, v, u (column reductions over M) ----------------
__global__ void qduv_kernel(const float* __restrict__ gamma, const float* __restrict__ delta,
                            const float* __restrict__ Are, const float* __restrict__ Aim)
{
    __shared__ float sq[4][64], sd[4][64];
    int t = threadIdx.x;
    int c = t & 63, s = t >> 6;
    int l = blockIdx.x * 64 + c;
    float q = 0.f, dd = 0.f;
    for (int m = s; m < Mdim; m += 4) {
        int idx = m * Ldim + l;
        float zr = g_Zre[idx], zi = g_Zim[idx];
        q  += zr * g_GZre[idx] + zi * g_GZim[idx];   // Re(conj(z) * (G z))
        dd += zr * Are[idx]   - zi * Aim[idx];       // Re(z * a)  (matches ref's d)
    }
    sq[s][c] = q; sd[s][c] = dd;
    __syncthreads();
    if (t < 64) {
        float qq = sq[0][t] + sq[1][t] + sq[2][t] + sq[3][t];
        float ds = sd[0][t] + sd[1][t] + sd[2][t] + sd[3][t];
        int ll = blockIdx.x * 64 + t;
        float v = qq / (ds + 1e-12f);
        float dl = 1.f / (1.f + expf(-delta[0]));
        float p = gamma[ll];
        g_v[ll] = v;
        g_u[ll] = p + dl * (v - p);
    }
}

// ---------------- LayerNorm + kv2 min/max (single block) ----------------
__global__ void ln_kernel(const float* __restrict__ ln_w, const float* __restrict__ ln_b,
                          const float* __restrict__ in_w, const float* __restrict__ in_b)
{
    __shared__ float red[512];
    __shared__ float s_mu, s_inv;
    int t = threadIdx.x;
    float s = 0.f;
    for (int i = t; i < Ldim; i += 512) s += g_u[i];
    red[t] = s; __syncthreads();
    for (int o = 256; o > 0; o >>= 1) { if (t < o) red[t] += red[t+o]; __syncthreads(); }
    if (t == 0) s_mu = red[0] / (float)Ldim;
    __syncthreads();
    float mu = s_mu;
    float s2 = 0.f;
    for (int i = t; i < Ldim; i += 512) { float d = g_u[i] - mu; s2 += d*d; }
    red[t] = s2; __syncthreads();
    for (int o = 256; o > 0; o >>= 1) { if (t < o) red[t] += red[t+o]; __syncthreads(); }
    if (t == 0) s_inv = rsqrtf(red[0] / (float)Ldim + 1e-5f);
    __syncthreads();
    float inv = s_inv;
    float w1 = in_w[1], b1 = in_b[1];
    float kmin = 3.4e38f, kmax = -3.4e38f;
    for (int i = t; i < Ldim; i += 512) {
        float up = (g_u[i] - mu) * inv * ln_w[i] + ln_b[i];
        g_up[i] = up;
        float k2 = (up * w1 + b1) * LOG2E_F;
        kmin = fminf(kmin, k2); kmax = fmaxf(kmax, k2);
    }
    red[t] = kmax; __syncthreads();
    for (int o = 256; o > 0; o >>= 1) { if (t < o) red[t] = fmaxf(red[t], red[t+o]); __syncthreads(); }
    if (t == 0) g_scal[2] = red[0];
    __syncthreads();
    red[t] = kmin; __syncthreads();
    for (int o = 256; o > 0; o >>= 1) { if (t < o) red[t] = fminf(red[t], red[t+o]); __syncthreads(); }
    if (t == 0) g_scal[1] = red[0];
}

// ---------------- attention: softmax over rank-1 scores ----------------
__global__ __launch_bounds__(256)
void attn_kernel(const float* __restrict__ in_w, const float* __restrict__ in_b,
                 const float* __restrict__ out_w, const float* __restrict__ out_b)
{
    __shared__ float skv2[Ldim];
    __shared__ float svv[Ldim];
    int t = threadIdx.x;
    float w0 = in_w[0], b0 = in_b[0];
    float w1 = in_w[1], b1 = in_b[1];
    float w2 = in_w[2], b2 = in_b[2];
    for (int j = t; j < Ldim; j += 256) {
        float up = g_up[j];
        skv2[j] = (up * w1 + b1) * LOG2E_F;
        svv[j]  = up * w2 + b2;
    }
    __syncthreads();
    float k2min = g_scal[1], k2max = g_scal[2];
    float ow = out_w[0], ob = out_b[0];
    int warp = t >> 5, lane = t & 31;
    #pragma unroll
    for (int r = 0; r < 4; r++) {
        int i = blockIdx.x * 32 + warp * 4 + r;
        float qv = g_up[i] * w0 + b0;
        float m2 = (qv >= 0.f) ? qv * k2max : qv * k2min;
        float den = 0.f, num = 0.f;
        for (int j = lane; j < Ldim; j += 32) {
            float arg = qv * skv2[j] - m2;
            float e;
            asm("ex2.approx.f32 %0, %1;" : "=f"(e) : "f"(arg));
            den += e;
            num = fmaf(e, svv[j], num);
        }
        den = warp_sum(den);
        num = warp_sum(num);
        if (lane == 0) g_attn[i] = (num / den) * ow + ob;
    }
}

// ---------------- gate matvec + final fuse ----------------
__global__ __launch_bounds__(256)
void final_kernel(const float* __restrict__ W, const float* __restrict__ gb,
                  const float* __restrict__ gamma, const float* __restrict__ lmbda,
                  float* __restrict__ out)
{
    int warp = threadIdx.x >> 5, lane = threadIdx.x & 31;
    int i = blockIdx.x * 8 + warp;
    const float4* Wr = (const float4*)(W + (size_t)i * Ldim);
    const float4* U4 = (const float4*)g_u;
    float acc = 0.f;
    for (int k = lane; k < Ldim/4; k += 32) {
        float4 w4 = Wr[k]; float4 u4 = U4[k];
        acc += w4.x*u4.x + w4.y*u4.y + w4.z*u4.z + w4.w*u4.w;
    }
    acc = warp_sum(acc);
    if (lane == 0) {
        float z = acc + gb[i];
        float g = 1.f / (1.f + expf(-z));
        float s = g * g_v[i] + (1.f - g) * gamma[i] + g_attn[i] - lmbda[0];
        out[i] = fmaxf(s, 0.f);
    }
}

// ---------------- launch ----------------
extern "C" void kernel_launch(void* const* d_in, const int* in_sizes, int n_in,
                              void* d_out, int out_size)
{
    const float* gamma  = (const float*)d_in[0];
    const float* A_re   = (const float*)d_in[1];
    const float* A_im   = (const float*)d_in[2];
    const float* X_re   = (const float*)d_in[3];
    const float* X_im   = (const float*)d_in[4];
    const float* ln_w   = (const float*)d_in[5];
    const float* ln_b   = (const float*)d_in[6];
    const float* in_w   = (const float*)d_in[7];
    const float* in_b   = (const float*)d_in[8];
    const float* out_w  = (const float*)d_in[9];
    const float* out_b  = (const float*)d_in[10];
    const float* gate_W = (const float*)d_in[11];
    const float* gate_b = (const float*)d_in[12];
    const float* delta  = (const float*)d_in[13];
    const float* lmbda  = (const float*)d_in[14];
    float* out = (float*)d_out;

    float *Rre,*Rim,*Gre,*Gim,*Xare,*Xaim,*Xbre,*Xbim,*Pre,*Pim,*pre,*pim,*Zre,*Zim,*GZre,*GZim;
    cudaGetSymbolAddress((void**)&Rre,  g_Rre);   cudaGetSymbolAddress((void**)&Rim,  g_Rim);
    cudaGetSymbolAddress((void**)&Gre,  g_Gre);   cudaGetSymbolAddress((void**)&Gim,  g_Gim);
    cudaGetSymbolAddress((void**)&Xare, g_Xa_re); cudaGetSymbolAddress((void**)&Xaim, g_Xa_im);
    cudaGetSymbolAddress((void**)&Xbre, g_Xb_re); cudaGetSymbolAddress((void**)&Xbim, g_Xb_im);
    cudaGetSymbolAddress((void**)&Pre,  g_P_re);  cudaGetSymbolAddress((void**)&Pim,  g_P_im);
    cudaGetSymbolAddress((void**)&pre,  g_part_re); cudaGetSymbolAddress((void**)&pim, g_part_im);
    cudaGetSymbolAddress((void**)&Zre,  g_Zre);   cudaGetSymbolAddress((void**)&Zim,  g_Zim);
    cudaGetSymbolAddress((void**)&GZre, g_GZre);  cudaGetSymbolAddress((void**)&GZim, g_GZim);

    init_scal_kernel<<<1, 1>>>();

    // R = (A*diag(gamma)) @ A^H + ridge*I   (K=4096, split 16)
    csyrk_part<<<dim3(4,4,16), 256>>>(pre, pim, A_re, A_im, gamma, Ldim, 256);
    reduce_RG<<<256, 256>>>(Rre, Rim, 16, 1);

    // G = X @ X^H   (K=2048, split 8)
    csyrk_part<<<dim3(4,4,8), 256>>>(pre, pim, X_re, X_im, nullptr, Tdim, 256);
    reduce_RG<<<256, 256>>>(Gre, Gim, 8, 0);

    // Newton-Schulz inverse of R
    rownorm_kernel<<<32, 256>>>();
    init_X0<<<256, 256>>>(Xare, Xaim);
    float *Xc_re = Xare, *Xc_im = Xaim, *Xn_re = Xbre, *Xn_im = Xbim;
    for (int it = 0; it < 12; ++it) {
        // P = R @ X
        cgemm_nn<32,32,32,2,2><<<dim3(8,8,4), 256>>>(pre, pim, Rre, Rim, Mdim,
                                                     Xc_re, Xc_im, Mdim, 64, Mdim*Mdim);
        reduce_sum<<<256, 256>>>(Pre, Pim, 4);
        // Xn = 2X - X @ P
        cgemm_nn<32,32,32,2,2><<<dim3(8,8,4), 256>>>(pre, pim, Xc_re, Xc_im, Mdim,
                                                     Pre, Pim, Mdim, 64, Mdim*Mdim);
        reduce_newton<<<256, 256>>>(Xn_re, Xn_im, Xc_re, Xc_im, 4);
        float* tmp;
        tmp = Xc_re; Xc_re = Xn_re; Xn_re = tmp;
        tmp = Xc_im; Xc_im = Xn_im; Xn_im = tmp;
    }

    // Z = Rinv @ A   [256 x 4096]
    cgemm_nn<64,64,32,4,4><<<dim3(64,4,1), 256>>>(Zre, Zim, Xc_re, Xc_im, Mdim,
                                                  A_re, A_im, Ldim, Mdim, 0);
    // GZ = G @ Z
    cgemm_nn<64,64,32,4,4><<<dim3(64,4,1), 256>>>(GZre, GZim, Gre, Gim, Mdim,
                                                  Zre, Zim, Ldim, Mdim, 0);

    // q, d, v, u
    qduv_kernel<<<64, 256>>>(gamma, delta, A_re, A_im);
    // LayerNorm + kv stats
    ln_kernel<<<1, 512>>>(ln_w, ln_b, in_w, in_b);
    // attention
    attn_kernel<<<128, 256>>>(in_w, in_b, out_w, out_b);
    // gate matvec + final
    final_kernel<<<512, 256>>>(gate_W, gate_b, gamma, lmbda, out);
}

// round 3
// speedup vs baseline: 1.0071x; 1.0071x over previous
#include <cuda_runtime.h>
#include <math.h>

#define Mdim 256
#define Ldim 4096
#define Tdim 2048

static const float kRIDGE = 0.01f;
#define LOG2E_F 1.4426950408889634f

// ---------------- device scratch (no allocations allowed) ----------------
__device__ float g_Rre[Mdim*Mdim], g_Rim[Mdim*Mdim];
__device__ float g_Gre[Mdim*Mdim], g_Gim[Mdim*Mdim];
__device__ float g_Xa_re[Mdim*Mdim], g_Xa_im[Mdim*Mdim];
__device__ float g_Xb_re[Mdim*Mdim], g_Xb_im[Mdim*Mdim];
__device__ float g_P_re[Mdim*Mdim], g_P_im[Mdim*Mdim];
__device__ float g_part_re[16*Mdim*Mdim], g_part_im[16*Mdim*Mdim];
__device__ float g_Zre[Mdim*Ldim], g_Zim[Mdim*Ldim];
__device__ float g_GZre[Mdim*Ldim], g_GZim[Mdim*Ldim];
__device__ float g_v[Ldim], g_u[Ldim], g_up[Ldim], g_attn[Ldim];
__device__ float g_scal[4];   // [0]=row-norm bound, [1]=kv2min, [2]=kv2max

__device__ __forceinline__ float warp_sum(float v) {
    #pragma unroll
    for (int o = 16; o > 0; o >>= 1) v += __shfl_xor_sync(0xffffffffu, v, o);
    return v;
}

// ---------------- init ----------------
__global__ void init_scal_kernel() {
    g_scal[0] = 0.f; g_scal[1] = 0.f; g_scal[2] = 0.f; g_scal[3] = 0.f;
}

// ---------------- C = (A*diag(w)) @ A^H  (partial over k-split) ----------------
// Output tile (64x64), K chunked via blockIdx.z. A is [256 x K] planar (re/im).
__global__ __launch_bounds__(256)
void csyrk_part(float* __restrict__ Pre, float* __restrict__ Pim,
                const float* __restrict__ Are, const float* __restrict__ Aim,
                const float* __restrict__ w, int lda, int kChunk)
{
    const int BM = 64, BN = 64, BK = 32, TM = 4, TN = 4;
    __shared__ float as_re[BK][BM+1], as_im[BK][BM+1];
    __shared__ float bs_re[BK][BN+1], bs_im[BK][BN+1];
    int i0 = blockIdx.y * BM, j0 = blockIdx.x * BN;
    int k0 = blockIdx.z * kChunk;
    int t  = threadIdx.x;
    int tx = t & 15, ty = t >> 4;
    float cre[TM][TN] = {}, cim[TM][TN] = {};

    for (int kb = 0; kb < kChunk; kb += BK) {
        #pragma unroll
        for (int e = t; e < BM*BK; e += 256) {
            int row = e >> 5, kk = e & 31;
            int g = (i0 + row) * lda + k0 + kb + kk;
            float ww = w ? w[k0 + kb + kk] : 1.0f;
            as_re[kk][row] = Are[g] * ww;
            as_im[kk][row] = Aim[g] * ww;
        }
        #pragma unroll
        for (int e = t; e < BN*BK; e += 256) {
            int col = e >> 5, kk = e & 31;
            int g = (j0 + col) * lda + k0 + kb + kk;
            bs_re[kk][col] = Are[g];
            bs_im[kk][col] = Aim[g];
        }
        __syncthreads();
        #pragma unroll 4
        for (int kk = 0; kk < BK; kk++) {
            float ar[TM], ai[TM], br[TN], bi[TN];
            #pragma unroll
            for (int i = 0; i < TM; i++) { ar[i] = as_re[kk][ty*TM+i]; ai[i] = as_im[kk][ty*TM+i]; }
            #pragma unroll
            for (int j = 0; j < TN; j++) { br[j] = bs_re[kk][tx*TN+j]; bi[j] = bs_im[kk][tx*TN+j]; }
            #pragma unroll
            for (int i = 0; i < TM; i++)
                #pragma unroll
                for (int j = 0; j < TN; j++) {
                    // a * conj(b)
                    cre[i][j] += ar[i]*br[j];
                    cre[i][j] += ai[i]*bi[j];
                    cim[i][j] += ai[i]*br[j];
                    cim[i][j] -= ar[i]*bi[j];
                }
        }
        __syncthreads();
    }
    size_t off = (size_t)blockIdx.z * (Mdim * Mdim);
    #pragma unroll
    for (int i = 0; i < TM; i++)
        #pragma unroll
        for (int j = 0; j < TN; j++) {
            int gi = i0 + ty*TM + i, gj = j0 + tx*TN + j;
            Pre[off + gi*Mdim + gj] = cre[i][j];
            Pim[off + gi*Mdim + gj] = cim[i][j];
        }
}

// sum k-split partials, optionally add ridge on diagonal
__global__ void reduce_RG(float* __restrict__ Cre, float* __restrict__ Cim,
                          int SK, int addRidge)
{
    int e = blockIdx.x * 256 + threadIdx.x;
    float sr = 0.f, si = 0.f;
    for (int z = 0; z < SK; z++) { sr += g_part_re[z*Mdim*Mdim + e]; si += g_part_im[z*Mdim*Mdim + e]; }
    if (addRidge && (e >> 8) == (e & 255)) sr += kRIDGE;
    Cre[e] = sr; Cim[e] = si;
}

// ---------------- Gershgorin bound: max row abs-sum of R ----------------
__global__ void rownorm_kernel() {
    int warp = threadIdx.x >> 5, lane = threadIdx.x & 31;
    int i = blockIdx.x * 8 + warp;
    float s = 0.f;
    for (int j = lane; j < Mdim; j += 32)
        s += fabsf(g_Rre[i*Mdim + j]) + fabsf(g_Rim[i*Mdim + j]);
    s = warp_sum(s);
    if (lane == 0) atomicMax((unsigned int*)&g_scal[0], __float_as_uint(s));
}

__global__ void init_X0(float* __restrict__ Xre, float* __restrict__ Xim) {
    int i = blockIdx.x, j = threadIdx.x;
    float inv = 1.0f / g_scal[0];
    Xre[i*Mdim + j] = (i == j) ? inv : 0.f;
    Xim[i*Mdim + j] = 0.f;
}

// ---------------- generic complex NN GEMM (planar), k-split partials ----------------
template<int BM, int BN, int BK, int TM, int TN>
__global__ __launch_bounds__(256)
void cgemm_nn(float* __restrict__ Cre, float* __restrict__ Cim,
              const float* __restrict__ Are, const float* __restrict__ Aim, int lda,
              const float* __restrict__ Bre, const float* __restrict__ Bim, int ldb,
              int kChunk, int MNpart)
{
    __shared__ float as_re[BK][BM+1], as_im[BK][BM+1];
    __shared__ float bs_re[BK][BN+1], bs_im[BK][BN+1];
    int i0 = blockIdx.y * BM, j0 = blockIdx.x * BN;
    int k0 = blockIdx.z * kChunk;
    int t  = threadIdx.x;
    int tx = t % (BN/TN), ty = t / (BN/TN);
    float cre[TM][TN] = {}, cim[TM][TN] = {};

    for (int kb = 0; kb < kChunk; kb += BK) {
        #pragma unroll
        for (int e = t; e < BM*BK; e += 256) {
            int row = e / BK, kk = e % BK;
            int g = (i0 + row) * lda + k0 + kb + kk;
            as_re[kk][row] = Are[g];
            as_im[kk][row] = Aim[g];
        }
        #pragma unroll
        for (int e = t; e < BK*BN; e += 256) {
            int kk = e / BN, col = e % BN;
            int g = (k0 + kb + kk) * ldb + j0 + col;
            bs_re[kk][col] = Bre[g];
            bs_im[kk][col] = Bim[g];
        }
        __syncthreads();
        #pragma unroll 4
        for (int kk = 0; kk < BK; kk++) {
            float ar[TM], ai[TM], br[TN], bi[TN];
            #pragma unroll
            for (int i = 0; i < TM; i++) { ar[i] = as_re[kk][ty*TM+i]; ai[i] = as_im[kk][ty*TM+i]; }
            #pragma unroll
            for (int j = 0; j < TN; j++) { br[j] = bs_re[kk][tx*TN+j]; bi[j] = bs_im[kk][tx*TN+j]; }
            #pragma unroll
            for (int i = 0; i < TM; i++)
                #pragma unroll
                for (int j = 0; j < TN; j++) {
                    cre[i][j] += ar[i]*br[j];
                    cre[i][j] -= ai[i]*bi[j];
                    cim[i][j] += ar[i]*bi[j];
                    cim[i][j] += ai[i]*br[j];
                }
        }
        __syncthreads();
    }
    size_t off = (size_t)blockIdx.z * MNpart;
    #pragma unroll
    for (int i = 0; i < TM; i++)
        #pragma unroll
        for (int j = 0; j < TN; j++) {
            int gi = i0 + ty*TM + i, gj = j0 + tx*TN + j;
            Cre[off + (size_t)gi*ldb + gj] = cre[i][j];
            Cim[off + (size_t)gi*ldb + gj] = cim[i][j];
        }
}

__global__ void reduce_sum(float* __restrict__ Cre, float* __restrict__ Cim, int SK) {
    int e = blockIdx.x * 256 + threadIdx.x;
    float sr = 0.f, si = 0.f;
    for (int z = 0; z < SK; z++) { sr += g_part_re[z*Mdim*Mdim + e]; si += g_part_im[z*Mdim*Mdim + e]; }
    Cre[e] = sr; Cim[e] = si;
}

// Xn = 2*X - sum_z part[z]
__global__ void reduce_newton(float* __restrict__ Xnre, float* __restrict__ Xnim,
                              const float* __restrict__ Xre, const float* __restrict__ Xim, int SK)
{
    int e = blockIdx.x * 256 + threadIdx.x;
    float sr = 0.f, si = 0.f;
    for (int z = 0; z < SK; z++) { sr += g_part_re[z*Mdim*Mdim + e]; si += g_part_im[z*Mdim*Mdim + e]; }
    Xnre[e] = 2.f*Xre[e] - sr;
    Xnim[e] = 2.f*Xim[e] - si;
}

// ---------------- q, d, v, u (column reductions over M) ----------------
__global__ void qduv_kernel(const float* __restrict__ gamma, const float* __restrict__ delta,
                            const float* __restrict__ Are, const float* __restrict__ Aim)
{
    __shared__ float sq[4][64], sd[4][64];
    int t = threadIdx.x;
    int c = t & 63, s = t >> 6;
    int l = blockIdx.x * 64 + c;
    float q = 0.f, dd = 0.f;
    for (int m = s; m < Mdim; m += 4) {
        int idx = m * Ldim + l;
        float zr = g_Zre[idx], zi = g_Zim[idx];
        q  += zr * g_GZre[idx] + zi * g_GZim[idx];   // Re(conj(z) * (G z))
        dd += zr * Are[idx]   - zi * Aim[idx];       // Re(z * a)  (matches ref's d)
    }
    sq[s][c] = q; sd[s][c] = dd;
    __syncthreads();
    if (t < 64) {
        float qq = sq[0][t] + sq[1][t] + sq[2][t] + sq[3][t];
        float ds = sd[0][t] + sd[1][t] + sd[2][t] + sd[3][t];
        int ll = blockIdx.x * 64 + t;
        float v = qq / (ds + 1e-12f);
        float dl = 1.f / (1.f + expf(-delta[0]));
        float p = gamma[ll];
        g_v[ll] = v;
        g_u[ll] = p + dl * (v - p);
    }
}

// ---------------- LayerNorm + kv2 min/max (single block) ----------------
__global__ void ln_kernel(const float* __restrict__ ln_w, const float* __restrict__ ln_b,
                          const float* __restrict__ in_w, const float* __restrict__ in_b)
{
    __shared__ float red[512];
    __shared__ float s_mu, s_inv;
    int t = threadIdx.x;
    float s = 0.f;
    for (int i = t; i < Ldim; i += 512) s += g_u[i];
    red[t] = s; __syncthreads();
    for (int o = 256; o > 0; o >>= 1) { if (t < o) red[t] += red[t+o]; __syncthreads(); }
    if (t == 0) s_mu = red[0] / (float)Ldim;
    __syncthreads();
    float mu = s_mu;
    float s2 = 0.f;
    for (int i = t; i < Ldim; i += 512) { float d = g_u[i] - mu; s2 += d*d; }
    red[t] = s2; __syncthreads();
    for (int o = 256; o > 0; o >>= 1) { if (t < o) red[t] += red[t+o]; __syncthreads(); }
    if (t == 0) s_inv = rsqrtf(red[0] / (float)Ldim + 1e-5f);
    __syncthreads();
    float inv = s_inv;
    float w1 = in_w[1], b1 = in_b[1];
    float kmin = 3.4e38f, kmax = -3.4e38f;
    for (int i = t; i < Ldim; i += 512) {
        float up = (g_u[i] - mu) * inv * ln_w[i] + ln_b[i];
        g_up[i] = up;
        float k2 = (up * w1 + b1) * LOG2E_F;
        kmin = fminf(kmin, k2); kmax = fmaxf(kmax, k2);
    }
    red[t] = kmax; __syncthreads();
    for (int o = 256; o > 0; o >>= 1) { if (t < o) red[t] = fmaxf(red[t], red[t+o]); __syncthreads(); }
    if (t == 0) g_scal[2] = red[0];
    __syncthreads();
    red[t] = kmin; __syncthreads();
    for (int o = 256; o > 0; o >>= 1) { if (t < o) red[t] = fminf(red[t], red[t+o]); __syncthreads(); }
    if (t == 0) g_scal[1] = red[0];
}

// ---------------- attention: softmax over rank-1 scores ----------------
__global__ __launch_bounds__(256)
void attn_kernel(const float* __restrict__ in_w, const float* __restrict__ in_b,
                 const float* __restrict__ out_w, const float* __restrict__ out_b)
{
    __shared__ float skv2[Ldim];
    __shared__ float svv[Ldim];
    int t = threadIdx.x;
    float w0 = in_w[0], b0 = in_b[0];
    float w1 = in_w[1], b1 = in_b[1];
    float w2 = in_w[2], b2 = in_b[2];
    for (int j = t; j < Ldim; j += 256) {
        float up = g_up[j];
        skv2[j] = (up * w1 + b1) * LOG2E_F;
        svv[j]  = up * w2 + b2;
    }
    __syncthreads();
    float k2min = g_scal[1], k2max = g_scal[2];
    float ow = out_w[0], ob = out_b[0];
    int warp = t >> 5, lane = t & 31;
    #pragma unroll
    for (int r = 0; r < 4; r++) {
        int i = blockIdx.x * 32 + warp * 4 + r;
        float qv = g_up[i] * w0 + b0;
        float m2 = (qv >= 0.f) ? qv * k2max : qv * k2min;
        float den = 0.f, num = 0.f;
        for (int j = lane; j < Ldim; j += 32) {
            float arg = qv * skv2[j] - m2;
            float e;
            asm("ex2.approx.f32 %0, %1;" : "=f"(e) : "f"(arg));
            den += e;
            num = fmaf(e, svv[j], num);
        }
        den = warp_sum(den);
        num = warp_sum(num);
        if (lane == 0) g_attn[i] = (num / den) * ow + ob;
    }
}

// ---------------- gate matvec + final fuse ----------------
__global__ __launch_bounds__(256)
void final_kernel(const float* __restrict__ W, const float* __restrict__ gb,
                  const float* __restrict__ gamma, const float* __restrict__ lmbda,
                  float* __restrict__ out)
{
    int warp = threadIdx.x >> 5, lane = threadIdx.x & 31;
    int i = blockIdx.x * 8 + warp;
    const float4* Wr = (const float4*)(W + (size_t)i * Ldim);
    const float4* U4 = (const float4*)g_u;
    float acc = 0.f;
    for (int k = lane; k < Ldim/4; k += 32) {
        float4 w4 = Wr[k]; float4 u4 = U4[k];
        acc += w4.x*u4.x + w4.y*u4.y + w4.z*u4.z + w4.w*u4.w;
    }
    acc = warp_sum(acc);
    if (lane == 0) {
        float z = acc + gb[i];
        float g = 1.f / (1.f + expf(-z));
        float s = g * g_v[i] + (1.f - g) * gamma[i] + g_attn[i] - lmbda[0];
        out[i] = fmaxf(s, 0.f);
    }
}

// ---------------- launch ----------------
extern "C" void kernel_launch(void* const* d_in, const int* in_sizes, int n_in,
                              void* d_out, int out_size)
{
    const float* gamma  = (const float*)d_in[0];
    const float* A_re   = (const float*)d_in[1];
    const float* A_im   = (const float*)d_in[2];
    const float* X_re   = (const float*)d_in[3];
    const float* X_im   = (const float*)d_in[4];
    const float* ln_w   = (const float*)d_in[5];
    const float* ln_b   = (const float*)d_in[6];
    const float* in_w   = (const float*)d_in[7];
    const float* in_b   = (const float*)d_in[8];
    const float* out_w  = (const float*)d_in[9];
    const float* out_b  = (const float*)d_in[10];
    const float* gate_W = (const float*)d_in[11];
    const float* gate_b = (const float*)d_in[12];
    const float* delta  = (const float*)d_in[13];
    const float* lmbda  = (const float*)d_in[14];
    float* out = (float*)d_out;

    float *Rre,*Rim,*Gre,*Gim,*Xare,*Xaim,*Xbre,*Xbim,*Pre,*Pim,*pre,*pim,*Zre,*Zim,*GZre,*GZim;
    cudaGetSymbolAddress((void**)&Rre,  g_Rre);   cudaGetSymbolAddress((void**)&Rim,  g_Rim);
    cudaGetSymbolAddress((void**)&Gre,  g_Gre);   cudaGetSymbolAddress((void**)&Gim,  g_Gim);
    cudaGetSymbolAddress((void**)&Xare, g_Xa_re); cudaGetSymbolAddress((void**)&Xaim, g_Xa_im);
    cudaGetSymbolAddress((void**)&Xbre, g_Xb_re); cudaGetSymbolAddress((void**)&Xbim, g_Xb_im);
    cudaGetSymbolAddress((void**)&Pre,  g_P_re);  cudaGetSymbolAddress((void**)&Pim,  g_P_im);
    cudaGetSymbolAddress((void**)&pre,  g_part_re); cudaGetSymbolAddress((void**)&pim, g_part_im);
    cudaGetSymbolAddress((void**)&Zre,  g_Zre);   cudaGetSymbolAddress((void**)&Zim,  g_Zim);
    cudaGetSymbolAddress((void**)&GZre, g_GZre);  cudaGetSymbolAddress((void**)&GZim, g_GZim);

    init_scal_kernel<<<1, 1>>>();

    // R = (A*diag(gamma)) @ A^H + ridge*I   (K=4096, split 16)
    csyrk_part<<<dim3(4,4,16), 256>>>(pre, pim, A_re, A_im, gamma, Ldim, 256);
    reduce_RG<<<256, 256>>>(Rre, Rim, 16, 1);

    // G = X @ X^H   (K=2048, split 8)
    csyrk_part<<<dim3(4,4,8), 256>>>(pre, pim, X_re, X_im, nullptr, Tdim, 256);
    reduce_RG<<<256, 256>>>(Gre, Gim, 8, 0);

    // Newton-Schulz inverse of R
    rownorm_kernel<<<32, 256>>>();
    init_X0<<<256, 256>>>(Xare, Xaim);
    float *Xc_re = Xare, *Xc_im = Xaim, *Xn_re = Xbre, *Xn_im = Xbim;
    for (int it = 0; it < 12; ++it) {
        // P = R @ X
        cgemm_nn<32,32,32,2,2><<<dim3(8,8,4), 256>>>(pre, pim, Rre, Rim, Mdim,
                                                     Xc_re, Xc_im, Mdim, 64, Mdim*Mdim);
        reduce_sum<<<256, 256>>>(Pre, Pim, 4);
        // Xn = 2X - X @ P
        cgemm_nn<32,32,32,2,2><<<dim3(8,8,4), 256>>>(pre, pim, Xc_re, Xc_im, Mdim,
                                                     Pre, Pim, Mdim, 64, Mdim*Mdim);
        reduce_newton<<<256, 256>>>(Xn_re, Xn_im, Xc_re, Xc_im, 4);
        float* tmp;
        tmp = Xc_re; Xc_re = Xn_re; Xn_re = tmp;
        tmp = Xc_im; Xc_im = Xn_im; Xn_im = tmp;
    }

    // Z = Rinv @ A   [256 x 4096]
    cgemm_nn<64,64,32,4,4><<<dim3(64,4,1), 256>>>(Zre, Zim, Xc_re, Xc_im, Mdim,
                                                  A_re, A_im, Ldim, Mdim, 0);
    // GZ = G @ Z
    cgemm_nn<64,64,32,4,4><<<dim3(64,4,1), 256>>>(GZre, GZim, Gre, Gim, Mdim,
                                                  Zre, Zim, Ldim, Mdim, 0);

    // q, d, v, u
    qduv_kernel<<<64, 256>>>(gamma, delta, A_re, A_im);
    // LayerNorm + kv stats
    ln_kernel<<<1, 512>>>(ln_w, ln_b, in_w, in_b);
    // attention
    attn_kernel<<<128, 256>>>(in_w, in_b, out_w, out_b);
    // gate matvec + final
    final_kernel<<<512, 256>>>(gate_W, gate_b, gamma, lmbda, out);
}

// round 8
// speedup vs baseline: 1.3092x; 1.3000x over previous
#include <cuda_runtime.h>
#include <cuda_bf16.h>
#include <math.h>
#include <stdint.h>

#define Mdim 256
#define Ldim 4096
#define Tdim 2048
#define LOG2E_F 1.4426950408889634f

// ---------------- device scratch ----------------
__device__ float g_Rre[Mdim*Mdim], g_Rim[Mdim*Mdim];
__device__ float g_Gre[Mdim*Mdim], g_Gim[Mdim*Mdim];
__device__ float g_Xa_re[Mdim*Mdim], g_Xa_im[Mdim*Mdim];
__device__ float g_Xb_re[Mdim*Mdim], g_Xb_im[Mdim*Mdim];
__device__ float g_P_re[Mdim*Mdim],  g_P_im[Mdim*Mdim];
__device__ float g_part_re[32*Mdim*Mdim], g_part_im[32*Mdim*Mdim];
__device__ float g_Atre[Ldim*Mdim], g_Atim[Ldim*Mdim];
__device__ float g_Ztre[Ldim*Mdim], g_Ztim[Ldim*Mdim];
__device__ float g_GZre[Ldim*Mdim], g_GZim[Ldim*Mdim];
__device__ float g_v[Ldim], g_u[Ldim], g_up[Ldim], g_attn[Ldim];
__device__ float g_scal[4];   // [0]=alpha  [1]=kv2min [2]=kv2max

__device__ __forceinline__ float warp_sum(float v) {
    #pragma unroll
    for (int o = 16; o > 0; o >>= 1) v += __shfl_xor_sync(0xffffffffu, v, o);
    return v;
}

// ---------------- smem helpers ----------------
__device__ __forceinline__ uint32_t smem_u32(const void* p) {
    uint32_t a;
    asm("{ .reg .u64 t; cvta.to.shared.u64 t, %1; cvt.u32.u64 %0, t; }" : "=r"(a) : "l"(p));
    return a;
}
__device__ __forceinline__ uint32_t lds32(uint32_t a) {
    uint32_t v;
    asm volatile("ld.shared.b32 %0, [%1];" : "=r"(v) : "r"(a));
    return v;
}
__device__ __forceinline__ void sts128(uint32_t a, uint32_t x, uint32_t y,
                                       uint32_t z, uint32_t w) {
    asm volatile("st.shared.v4.b32 [%0], {%1,%2,%3,%4};"
                 :: "r"(a), "r"(x), "r"(y), "r"(z), "r"(w) : "memory");
}
__device__ __forceinline__ uint32_t cvt_tf32(float x) {
    uint32_t r;
    asm("cvt.rna.tf32.f32 %0, %1;" : "=r"(r) : "f"(x));
    return r;
}
#define MMAT32(d, a, b) \
    asm volatile("mma.sync.aligned.m16n8k8.row.col.f32.tf32.tf32.f32 " \
        "{%0,%1,%2,%3},{%4,%5,%6,%7},{%8,%9},{%0,%1,%2,%3};" \
        : "+f"((d)[0]), "+f"((d)[1]), "+f"((d)[2]), "+f"((d)[3]) \
        : "r"((a)[0]), "r"((a)[1]), "r"((a)[2]), "r"((a)[3]), "r"((b)[0]), "r"((b)[1]))

#define PITCHB 144
#define PLSZ   18432
#define ENG_SMEM (8*PLSZ)

// convert one 128x32 fp32 tile -> tf32 hi/lo planes in smem (sign/weight folded)
__device__ __forceinline__ void conv_tile(uint32_t sa, int th, int tl,
                                          const float* __restrict__ src, int row0, int ld,
                                          int k0, const float* __restrict__ w, float sgn)
{
    int tid = threadIdx.x;
    uint32_t hb = sa + th*PLSZ, lb = sa + tl*PLSZ;
    #pragma unroll
    for (int p = 0; p < 4; p++) {
        int idx = tid + p*256;
        int row = idx >> 3, c4 = idx & 7;
        float4 v = *(const float4*)(src + (size_t)(row0+row)*ld + k0 + c4*4);
        if (w) {
            float4 wv = *(const float4*)(w + k0 + c4*4);
            v.x *= wv.x; v.y *= wv.y; v.z *= wv.z; v.w *= wv.w;
        }
        v.x *= sgn; v.y *= sgn; v.z *= sgn; v.w *= sgn;
        uint32_t h0 = cvt_tf32(v.x), h1 = cvt_tf32(v.y);
        uint32_t h2 = cvt_tf32(v.z), h3 = cvt_tf32(v.w);
        uint32_t l0 = cvt_tf32(v.x - __uint_as_float(h0));
        uint32_t l1 = cvt_tf32(v.y - __uint_as_float(h1));
        uint32_t l2 = cvt_tf32(v.z - __uint_as_float(h2));
        uint32_t l3 = cvt_tf32(v.w - __uint_as_float(h3));
        uint32_t off = row*PITCHB + c4*16;
        sts128(hb + off, h0, h1, h2, h3);
        sts128(lb + off, l0, l1, l2, l3);
    }
}

// ============================================================================
// split-tf32 complex GEMM via mma.sync m16n8k8:
//   D[i,j] = sum_k P[i,k] * op(Q[j,k]) ; conj: op=conj, else identity.
//   128x128 tile per CTA; blockIdx.z = plane (bit0) + 2*kslice.
// ============================================================================
__global__ __launch_bounds__(256, 1)
void cgemm_mma(const float* __restrict__ Pre, const float* __restrict__ Pim, int ldp,
               const float* __restrict__ Qre, const float* __restrict__ Qim, int ldq,
               float* __restrict__ Cre, float* __restrict__ Cim, int ldc,
               int Kper, int conj, const float* __restrict__ w, int partElems)
{
    extern __shared__ char dsm[];
    uint32_t sa = smem_u32(dsm);
    int tid = threadIdx.x;
    int wid = tid >> 5, lane = tid & 31;
    int g = lane >> 2, t4 = lane & 3;
    int warpM = wid >> 2, warpN = wid & 3;
    int i0 = blockIdx.y * 128, j0 = blockIdx.x * 128;
    int plane = blockIdx.z & 1, ks = blockIdx.z >> 1;

    const float* A0 = (conj && plane) ? Pim : Pre;
    const float* A1 = (conj && plane) ? Pre : Pim;
    float s1 = ((conj && plane) || (!conj && !plane)) ? -1.f : 1.f;
    const float* B0 = (!conj && plane) ? Qim : Qre;
    const float* B1 = (!conj && plane) ? Qre : Qim;

    float acc[4][4][4] = {};

    int nCh = Kper >> 5;
    for (int ch = 0; ch < nCh; ch++) {
        int k0 = ks * Kper + ch * 32;
        conv_tile(sa, 0, 1, A0, i0, ldp, k0, w, 1.f);
        conv_tile(sa, 2, 3, A1, i0, ldp, k0, w, s1);
        conv_tile(sa, 4, 5, B0, j0, ldq, k0, (const float*)0, 1.f);
        conv_tile(sa, 6, 7, B1, j0, ldq, k0, (const float*)0, 1.f);
        __syncthreads();

        const int ta[6] = {0, 0, 1, 2, 2, 3};
        const int tb[6] = {4, 5, 4, 6, 7, 6};
        #pragma unroll
        for (int ps = 0; ps < 6; ps++) {
            uint32_t ab = sa + ta[ps]*PLSZ;
            uint32_t bb = sa + tb[ps]*PLSZ;
            #pragma unroll
            for (int kk = 0; kk < 4; kk++) {
                uint32_t afr[4][4], bfr[4][2];
                #pragma unroll
                for (int am = 0; am < 4; am++) {
                    uint32_t r0 = ab + (warpM*64 + am*16 + g)*PITCHB + (kk*8 + t4)*4;
                    afr[am][0] = lds32(r0);
                    afr[am][1] = lds32(r0 + 8*PITCHB);
                    afr[am][2] = lds32(r0 + 16);
                    afr[am][3] = lds32(r0 + 8*PITCHB + 16);
                }
                #pragma unroll
                for (int bn = 0; bn < 4; bn++) {
                    uint32_t r0 = bb + (warpN*32 + bn*8 + g)*PITCHB + (kk*8 + t4)*4;
                    bfr[bn][0] = lds32(r0);
                    bfr[bn][1] = lds32(r0 + 16);
                }
                #pragma unroll
                for (int am = 0; am < 4; am++)
                    #pragma unroll
                    for (int bn = 0; bn < 4; bn++)
                        MMAT32(acc[am][bn], afr[am], bfr[bn]);
            }
        }
        __syncthreads();
    }

    float* dst = plane ? Cim : Cre;
    size_t zoff = (size_t)ks * partElems;
    #pragma unroll
    for (int am = 0; am < 4; am++) {
        #pragma unroll
        for (int bn = 0; bn < 4; bn++) {
            int r = i0 + warpM*64 + am*16 + g;
            int c = j0 + warpN*32 + bn*8 + 2*t4;
            float2 v0 = make_float2(acc[am][bn][0], acc[am][bn][1]);
            float2 v1 = make_float2(acc[am][bn][2], acc[am][bn][3]);
            *(float2*)(dst + zoff + (size_t)r*ldc + c) = v0;
            *(float2*)(dst + zoff + (size_t)(r+8)*ldc + c) = v1;
        }
    }
}

// ---------------- fp32 csyrk: C = (A*diag(w)) @ A^H partials ----------------
__global__ __launch_bounds__(256)
void csyrk_part(float* __restrict__ Pre, float* __restrict__ Pim,
                const float* __restrict__ Are, const float* __restrict__ Aim,
                const float* __restrict__ w, int lda, int kChunk)
{
    const int BM = 64, BN = 64, BK = 32, TM = 4, TN = 4;
    __shared__ float as_re[BK][BM+1], as_im[BK][BM+1];
    __shared__ float bs_re[BK][BN+1], bs_im[BK][BN+1];
    int i0 = blockIdx.y * BM, j0 = blockIdx.x * BN;
    int k0 = blockIdx.z * kChunk;
    int t  = threadIdx.x;
    int tx = t & 15, ty = t >> 4;
    float cre[TM][TN] = {}, cim[TM][TN] = {};

    for (int kb = 0; kb < kChunk; kb += BK) {
        #pragma unroll
        for (int e = t; e < BM*BK; e += 256) {
            int row = e >> 5, kk = e & 31;
            int g = (i0 + row) * lda + k0 + kb + kk;
            float ww = w ? w[k0 + kb + kk] : 1.0f;
            as_re[kk][row] = Are[g] * ww;
            as_im[kk][row] = Aim[g] * ww;
        }
        #pragma unroll
        for (int e = t; e < BN*BK; e += 256) {
            int col = e >> 5, kk = e & 31;
            int g = (j0 + col) * lda + k0 + kb + kk;
            bs_re[kk][col] = Are[g];
            bs_im[kk][col] = Aim[g];
        }
        __syncthreads();
        #pragma unroll 4
        for (int kk = 0; kk < BK; kk++) {
            float ar[TM], ai[TM], br[TN], bi[TN];
            #pragma unroll
            for (int i = 0; i < TM; i++) { ar[i] = as_re[kk][ty*TM+i]; ai[i] = as_im[kk][ty*TM+i]; }
            #pragma unroll
            for (int j = 0; j < TN; j++) { br[j] = bs_re[kk][tx*TN+j]; bi[j] = bs_im[kk][tx*TN+j]; }
            #pragma unroll
            for (int i = 0; i < TM; i++)
                #pragma unroll
                for (int j = 0; j < TN; j++) {
                    cre[i][j] += ar[i]*br[j];
                    cre[i][j] += ai[i]*bi[j];
                    cim[i][j] += ai[i]*br[j];
                    cim[i][j] -= ar[i]*bi[j];
                }
        }
        __syncthreads();
    }
    size_t off = (size_t)blockIdx.z * (Mdim * Mdim);
    #pragma unroll
    for (int i = 0; i < TM; i++)
        #pragma unroll
        for (int j = 0; j < TN; j++) {
            int gi = i0 + ty*TM + i, gj = j0 + tx*TN + j;
            Pre[off + gi*Mdim + gj] = cre[i][j];
            Pim[off + gi*Mdim + gj] = cim[i][j];
        }
}

// ---------------- proven fp32 SIMT complex NN GEMM ----------------
template<int BM, int BN, int BK, int TM, int TN>
__global__ __launch_bounds__(256)
void cgemm_nn(float* __restrict__ Cre, float* __restrict__ Cim,
              const float* __restrict__ Are, const float* __restrict__ Aim, int lda,
              const float* __restrict__ Bre, const float* __restrict__ Bim, int ldb,
              int kChunk, int MNpart)
{
    __shared__ float as_re[BK][BM+1], as_im[BK][BM+1];
    __shared__ float bs_re[BK][BN+1], bs_im[BK][BN+1];
    int i0 = blockIdx.y * BM, j0 = blockIdx.x * BN;
    int k0 = blockIdx.z * kChunk;
    int t  = threadIdx.x;
    int tx = t % (BN/TN), ty = t / (BN/TN);
    float cre[TM][TN] = {}, cim[TM][TN] = {};

    for (int kb = 0; kb < kChunk; kb += BK) {
        #pragma unroll
        for (int e = t; e < BM*BK; e += 256) {
            int row = e / BK, kk = e % BK;
            int g = (i0 + row) * lda + k0 + kb + kk;
            as_re[kk][row] = Are[g];
            as_im[kk][row] = Aim[g];
        }
        #pragma unroll
        for (int e = t; e < BK*BN; e += 256) {
            int kk = e / BN, col = e % BN;
            int g = (k0 + kb + kk) * ldb + j0 + col;
            bs_re[kk][col] = Bre[g];
            bs_im[kk][col] = Bim[g];
        }
        __syncthreads();
        #pragma unroll 4
        for (int kk = 0; kk < BK; kk++) {
            float ar[TM], ai[TM], br[TN], bi[TN];
            #pragma unroll
            for (int i = 0; i < TM; i++) { ar[i] = as_re[kk][ty*TM+i]; ai[i] = as_im[kk][ty*TM+i]; }
            #pragma unroll
            for (int j = 0; j < TN; j++) { br[j] = bs_re[kk][tx*TN+j]; bi[j] = bs_im[kk][tx*TN+j]; }
            #pragma unroll
            for (int i = 0; i < TM; i++)
                #pragma unroll
                for (int j = 0; j < TN; j++) {
                    cre[i][j] += ar[i]*br[j];
                    cre[i][j] -= ai[i]*bi[j];
                    cim[i][j] += ar[i]*bi[j];
                    cim[i][j] += ai[i]*br[j];
                }
        }
        __syncthreads();
    }
    size_t off = (size_t)blockIdx.z * MNpart;
    #pragma unroll
    for (int i = 0; i < TM; i++)
        #pragma unroll
        for (int j = 0; j < TN; j++) {
            int gi = i0 + ty*TM + i, gj = j0 + tx*TN + j;
            Cre[off + (size_t)gi*ldb + gj] = cre[i][j];
            Cim[off + (size_t)gi*ldb + gj] = cim[i][j];
        }
}

// ---------------- reduces ----------------
__global__ void reduce_RG(float* __restrict__ Cre, float* __restrict__ Cim, int SK, int ridge) {
    int e = blockIdx.x * 256 + threadIdx.x;
    float sr = 0.f, si = 0.f;
    for (int z = 0; z < SK; z++) { sr += g_part_re[z*65536 + e]; si += g_part_im[z*65536 + e]; }
    if (ridge && (e >> 8) == (e & 255)) sr += 0.01f;
    Cre[e] = sr; Cim[e] = si;
}
__global__ void reduce_sum(float* __restrict__ Cre, float* __restrict__ Cim, int SK) {
    int e = blockIdx.x * 256 + threadIdx.x;
    float sr = 0.f, si = 0.f;
    for (int z = 0; z < SK; z++) { sr += g_part_re[z*65536 + e]; si += g_part_im[z*65536 + e]; }
    Cre[e] = sr; Cim[e] = si;
}
__global__ void reduce_newton(float* __restrict__ Xnre, float* __restrict__ Xnim,
                              const float* __restrict__ Xre, const float* __restrict__ Xim, int SK)
{
    int e = blockIdx.x * 256 + threadIdx.x;
    float sr = 0.f, si = 0.f;
    for (int z = 0; z < SK; z++) { sr += g_part_re[z*65536 + e]; si += g_part_im[z*65536 + e]; }
    Xnre[e] = 2.f*Xre[e] - sr;
    Xnim[e] = 2.f*Xim[e] - si;
}

// ---------------- alpha = tr(R)/||R||_F^2 ; X0 = alpha*I ----------------
__global__ void trace_alpha() {
    __shared__ float red[1024];
    __shared__ float s_fro;
    int t = threadIdx.x;
    float fro = 0.f;
    for (int e = t; e < 65536; e += 1024) {
        float a = g_Rre[e], b = g_Rim[e];
        fro += a*a + b*b;
    }
    red[t] = fro; __syncthreads();
    for (int o = 512; o > 0; o >>= 1) { if (t < o) red[t] += red[t+o]; __syncthreads(); }
    if (t == 0) s_fro = red[0];
    __syncthreads();
    float tr = 0.f;
    for (int i = t; i < 256; i += 1024) tr += g_Rre[i*257];
    red[t] = tr; __syncthreads();
    for (int o = 512; o > 0; o >>= 1) { if (t < o) red[t] += red[t+o]; __syncthreads(); }
    if (t == 0) g_scal[0] = red[0] / s_fro;
}
__global__ void init_X0(float* __restrict__ Xre, float* __restrict__ Xim) {
    int i = blockIdx.x, j = threadIdx.x;
    float a = g_scal[0];
    Xre[i*Mdim + j] = (i == j) ? a : 0.f;
    Xim[i*Mdim + j] = 0.f;
}

// ---------------- Bc = conj(symmetrize(Rinv)) ----------------
__global__ void symm_conj(const float* __restrict__ Xre, const float* __restrict__ Xim,
                          float* __restrict__ Bre, float* __restrict__ Bim) {
    int e = blockIdx.x * 256 + threadIdx.x;
    int i = e >> 8, j = e & 255;
    Bre[e] = 0.5f * (Xre[i*256 + j] + Xre[j*256 + i]);
    Bim[e] = 0.5f * (Xim[j*256 + i] - Xim[i*256 + j]);
}

// ---------------- transpose A -> At [L][M] ----------------
__global__ void transposeA(const float* __restrict__ Are, const float* __restrict__ Aim) {
    __shared__ float t0[32][33], t1[32][33];
    int lb = blockIdx.x * 32, mb = blockIdx.y * 32;
    int x = threadIdx.x, y = threadIdx.y;
    for (int yy = y; yy < 32; yy += 8) {
        t0[yy][x] = Are[(size_t)(mb+yy)*Ldim + lb + x];
        t1[yy][x] = Aim[(size_t)(mb+yy)*Ldim + lb + x];
    }
    __syncthreads();
    for (int yy = y; yy < 32; yy += 8) {
        g_Atre[(size_t)(lb+yy)*Mdim + mb + x] = t0[x][yy];
        g_Atim[(size_t)(lb+yy)*Mdim + mb + x] = t1[x][yy];
    }
}

// ---------------- q, d, v, u (transposed layout) ----------------
__global__ __launch_bounds__(256)
void qduv_kernel(const float* __restrict__ gamma, const float* __restrict__ delta) {
    int wid = threadIdx.x >> 5, lane = threadIdx.x & 31;
    int l = blockIdx.x * 8 + wid;
    const float4* zr  = (const float4*)(g_Ztre + (size_t)l*Mdim);
    const float4* zi  = (const float4*)(g_Ztim + (size_t)l*Mdim);
    const float4* gr  = (const float4*)(g_GZre + (size_t)l*Mdim);
    const float4* gi  = (const float4*)(g_GZim + (size_t)l*Mdim);
    const float4* ar  = (const float4*)(g_Atre + (size_t)l*Mdim);
    const float4* ai  = (const float4*)(g_Atim + (size_t)l*Mdim);
    float q = 0.f, d = 0.f;
    #pragma unroll
    for (int it = 0; it < 2; it++) {
        int k = lane + it*32;
        float4 a = zr[k], b = zi[k], c = gr[k], e = gi[k], f = ar[k], g2 = ai[k];
        q += a.x*c.x + a.y*c.y + a.z*c.z + a.w*c.w
           + b.x*e.x + b.y*e.y + b.z*e.z + b.w*e.w;
        d += a.x*f.x + a.y*f.y + a.z*f.z + a.w*f.w
           - (b.x*g2.x + b.y*g2.y + b.z*g2.z + b.w*g2.w);
    }
    q = warp_sum(q); d = warp_sum(d);
    if (lane == 0) {
        float v = q / (d + 1e-12f);
        float dl = 1.f / (1.f + expf(-delta[0]));
        float p = gamma[l];
        g_v[l] = v;
        g_u[l] = p + dl * (v - p);
    }
}

// ---------------- LayerNorm + kv stats ----------------
__global__ void ln_kernel(const float* __restrict__ ln_w, const float* __restrict__ ln_b,
                          const float* __restrict__ in_w, const float* __restrict__ in_b)
{
    __shared__ float red[512];
    __shared__ float s_mu, s_inv;
    int t = threadIdx.x;
    float s = 0.f;
    for (int i = t; i < Ldim; i += 512) s += g_u[i];
    red[t] = s; __syncthreads();
    for (int o = 256; o > 0; o >>= 1) { if (t < o) red[t] += red[t+o]; __syncthreads(); }
    if (t == 0) s_mu = red[0] / (float)Ldim;
    __syncthreads();
    float mu = s_mu, s2 = 0.f;
    for (int i = t; i < Ldim; i += 512) { float d = g_u[i] - mu; s2 += d*d; }
    red[t] = s2; __syncthreads();
    for (int o = 256; o > 0; o >>= 1) { if (t < o) red[t] += red[t+o]; __syncthreads(); }
    if (t == 0) s_inv = rsqrtf(red[0] / (float)Ldim + 1e-5f);
    __syncthreads();
    float inv = s_inv;
    float w1 = in_w[1], b1 = in_b[1];
    float kmin = 3.4e38f, kmax = -3.4e38f;
    for (int i = t; i < Ldim; i += 512) {
        float up = (g_u[i] - mu) * inv * ln_w[i] + ln_b[i];
        g_up[i] = up;
        float k2 = (up * w1 + b1) * LOG2E_F;
        kmin = fminf(kmin, k2); kmax = fmaxf(kmax, k2);
    }
    red[t] = kmax; __syncthreads();
    for (int o = 256; o > 0; o >>= 1) { if (t < o) red[t] = fmaxf(red[t], red[t+o]); __syncthreads(); }
    if (t == 0) g_scal[2] = red[0];
    __syncthreads();
    red[t] = kmin; __syncthreads();
    for (int o = 256; o > 0; o >>= 1) { if (t < o) red[t] = fminf(red[t], red[t+o]); __syncthreads(); }
    if (t == 0) g_scal[1] = red[0];
}

// ---------------- attention (rank-1 softmax) ----------------
__global__ __launch_bounds__(256)
void attn_kernel(const float* __restrict__ in_w, const float* __restrict__ in_b,
                 const float* __restrict__ out_w, const float* __restrict__ out_b)
{
    __shared__ float skv2[Ldim];
    __shared__ float svv[Ldim];
    int t = threadIdx.x;
    float w0 = in_w[0], b0 = in_b[0];
    float w1 = in_w[1], b1 = in_b[1];
    float w2 = in_w[2], b2 = in_b[2];
    for (int j = t; j < Ldim; j += 256) {
        float up = g_up[j];
        skv2[j] = (up * w1 + b1) * LOG2E_F;
        svv[j]  = up * w2 + b2;
    }
    __syncthreads();
    float k2min = g_scal[1], k2max = g_scal[2];
    float ow = out_w[0], ob = out_b[0];
    int warp = t >> 5, lane = t & 31;
    #pragma unroll
    for (int r = 0; r < 4; r++) {
        int i = blockIdx.x * 32 + warp * 4 + r;
        float qv = g_up[i] * w0 + b0;
        float m2 = (qv >= 0.f) ? qv * k2max : qv * k2min;
        float den = 0.f, num = 0.f;
        for (int j = lane; j < Ldim; j += 32) {
            float arg = qv * skv2[j] - m2;
            float e;
            asm("ex2.approx.f32 %0, %1;" : "=f"(e) : "f"(arg));
            den += e;
            num = fmaf(e, svv[j], num);
        }
        den = warp_sum(den); num = warp_sum(num);
        if (lane == 0) g_attn[i] = (num / den) * ow + ob;
    }
}

// ---------------- gate matvec + final fuse ----------------
__global__ __launch_bounds__(256)
void final_kernel(const float* __restrict__ W, const float* __restrict__ gb,
                  const float* __restrict__ gamma, const float* __restrict__ lmbda,
                  float* __restrict__ out)
{
    int warp = threadIdx.x >> 5, lane = threadIdx.x & 31;
    int i = blockIdx.x * 8 + warp;
    const float4* Wr = (const float4*)(W + (size_t)i * Ldim);
    const float4* U4 = (const float4*)g_u;
    float acc = 0.f;
    for (int k = lane; k < Ldim/4; k += 32) {
        float4 w4 = Wr[k]; float4 u4 = U4[k];
        acc += w4.x*u4.x + w4.y*u4.y + w4.z*u4.z + w4.w*u4.w;
    }
    acc = warp_sum(acc);
    if (lane == 0) {
        float z = acc + gb[i];
        float g = 1.f / (1.f + expf(-z));
        float s = g * g_v[i] + (1.f - g) * gamma[i] + g_attn[i] - lmbda[0];
        out[i] = fmaxf(s, 0.f);
    }
}

// ---------------- launch ----------------
extern "C" void kernel_launch(void* const* d_in, const int* in_sizes, int n_in,
                              void* d_out, int out_size)
{
    const float* gamma  = (const float*)d_in[0];
    const float* A_re   = (const float*)d_in[1];
    const float* A_im   = (const float*)d_in[2];
    const float* X_re   = (const float*)d_in[3];
    const float* X_im   = (const float*)d_in[4];
    const float* ln_w   = (const float*)d_in[5];
    const float* ln_b   = (const float*)d_in[6];
    const float* in_w   = (const float*)d_in[7];
    const float* in_b   = (const float*)d_in[8];
    const float* out_w  = (const float*)d_in[9];
    const float* out_b  = (const float*)d_in[10];
    const float* gate_W = (const float*)d_in[11];
    const float* gate_b = (const float*)d_in[12];
    const float* delta  = (const float*)d_in[13];
    const float* lmbda  = (const float*)d_in[14];
    float* out = (float*)d_out;

    cudaFuncSetAttribute(cgemm_mma, cudaFuncAttributeMaxDynamicSharedMemorySize, ENG_SMEM);

    float *Rre,*Rim,*Gre,*Gim,*Xare,*Xaim,*Xbre,*Xbim,*Pre,*Pim;
    float *pre,*pim,*Atre,*Atim,*Ztre,*Ztim,*GZre,*GZim;
    cudaGetSymbolAddress((void**)&Rre,  g_Rre);   cudaGetSymbolAddress((void**)&Rim,  g_Rim);
    cudaGetSymbolAddress((void**)&Gre,  g_Gre);   cudaGetSymbolAddress((void**)&Gim,  g_Gim);
    cudaGetSymbolAddress((void**)&Xare, g_Xa_re); cudaGetSymbolAddress((void**)&Xaim, g_Xa_im);
    cudaGetSymbolAddress((void**)&Xbre, g_Xb_re); cudaGetSymbolAddress((void**)&Xbim, g_Xb_im);
    cudaGetSymbolAddress((void**)&Pre,  g_P_re);  cudaGetSymbolAddress((void**)&Pim,  g_P_im);
    cudaGetSymbolAddress((void**)&pre,  g_part_re); cudaGetSymbolAddress((void**)&pim, g_part_im);
    cudaGetSymbolAddress((void**)&Atre, g_Atre);  cudaGetSymbolAddress((void**)&Atim, g_Atim);
    cudaGetSymbolAddress((void**)&Ztre, g_Ztre);  cudaGetSymbolAddress((void**)&Ztim, g_Ztim);
    cudaGetSymbolAddress((void**)&GZre, g_GZre);  cudaGetSymbolAddress((void**)&GZim, g_GZim);

    // At = A^T (planar)
    transposeA<<<dim3(128, 8), dim3(32, 8)>>>(A_re, A_im);

    // R = (A*diag(gamma)) A^H + ridge I : fp32 csyrk, 32-way k-split
    csyrk_part<<<dim3(4,4,32), 256>>>(pre, pim, A_re, A_im, gamma, Ldim, 128);
    reduce_RG<<<256, 256>>>(Rre, Rim, 32, 1);

    // G = X X^H : tf32-split MMA (benign q-path), 16-way k-split
    cgemm_mma<<<dim3(2,2,32), 256, ENG_SMEM>>>(X_re, X_im, Tdim, X_re, X_im, Tdim,
                                               pre, pim, Mdim, 128, 1, nullptr, 65536);
    reduce_RG<<<256, 256>>>(Gre, Gim, 16, 0);

    // alpha and X0 = alpha*I
    trace_alpha<<<1, 1024>>>();
    init_X0<<<256, 256>>>(Xare, Xaim);

    // order-2 Newton (fp32 SIMT, 64x64 tiles): Xn = 2X - X(RX), 7 iterations
    float *Xc_re = Xare, *Xc_im = Xaim, *Xn_re = Xbre, *Xn_im = Xbim;
    for (int it = 0; it < 7; ++it) {
        cgemm_nn<64,64,32,4,4><<<dim3(4,4,8), 256>>>(pre, pim, Rre, Rim, Mdim,
                                                     Xc_re, Xc_im, Mdim, 32, 65536);
        reduce_sum<<<256, 256>>>(Pre, Pim, 8);
        cgemm_nn<64,64,32,4,4><<<dim3(4,4,8), 256>>>(pre, pim, Xc_re, Xc_im, Mdim,
                                                     Pre, Pim, Mdim, 32, 65536);
        reduce_newton<<<256, 256>>>(Xn_re, Xn_im, Xc_re, Xc_im, 8);
        float* tmp;
        tmp = Xc_re; Xc_re = Xn_re; Xn_re = tmp;
        tmp = Xc_im; Xc_im = Xn_im; Xn_im = tmp;
    }

    // Bc = conj(symmetrized Rinv)  (into g_P, free after Newton)
    symm_conj<<<256, 256>>>(Xc_re, Xc_im, Pre, Pim);

    // Zt[l,m] = sum_k At[l,k] * Bc[k,m]   (fp32 SIMT NN — d-chain precision)
    cgemm_nn<64,64,32,4,4><<<dim3(4,64,1), 256>>>(Ztre, Ztim, Atre, Atim, Mdim,
                                                  Pre, Pim, Mdim, 256, 0);

    // GZt[l,m] = sum_k Zt[l,k] * G[m,k]   (tf32-split MMA, benign q-path)
    cgemm_mma<<<dim3(2,32,2), 256, ENG_SMEM>>>(Ztre, Ztim, Mdim, Gre, Gim, Mdim,
                                               GZre, GZim, Mdim, 256, 0, nullptr, 0);

    qduv_kernel<<<512, 256>>>(gamma, delta);
    ln_kernel<<<1, 512>>>(ln_w, ln_b, in_w, in_b);
    attn_kernel<<<128, 256>>>(in_w, in_b, out_w, out_b);
    final_kernel<<<512, 256>>>(gate_W, gate_b, gamma, lmbda, out);
}

// round 12
// speedup vs baseline: 1.3228x; 1.0103x over previous
#include <cuda_runtime.h>
#include <cuda_bf16.h>
#include <math.h>
#include <stdint.h>

#define Mdim 256
#define Ldim 4096
#define Tdim 2048
#define LOG2E_F 1.4426950408889634f

// ---------------- device scratch ----------------
__device__ float g_Rre[Mdim*Mdim], g_Rim[Mdim*Mdim];
__device__ float g_Gre[Mdim*Mdim], g_Gim[Mdim*Mdim];
__device__ float g_Xa_re[Mdim*Mdim], g_Xa_im[Mdim*Mdim];
__device__ float g_Xb_re[Mdim*Mdim], g_Xb_im[Mdim*Mdim];
__device__ float g_P_re[Mdim*Mdim],  g_P_im[Mdim*Mdim];
__device__ float g_part_re[32*Mdim*Mdim], g_part_im[32*Mdim*Mdim];
__device__ float g_Atre[Ldim*Mdim], g_Atim[Ldim*Mdim];
__device__ float g_Ztre[Ldim*Mdim], g_Ztim[Ldim*Mdim];
__device__ float g_GZre[Ldim*Mdim], g_GZim[Ldim*Mdim];
__device__ float g_v[Ldim], g_u[Ldim], g_up[Ldim], g_attn[Ldim];
__device__ float g_scal[4];   // [0]=alpha  [1]=kv2min [2]=kv2max

__device__ __forceinline__ float warp_sum(float v) {
    #pragma unroll
    for (int o = 16; o > 0; o >>= 1) v += __shfl_xor_sync(0xffffffffu, v, o);
    return v;
}

// ---------------- smem helpers ----------------
__device__ __forceinline__ uint32_t smem_u32(const void* p) {
    uint32_t a;
    asm("{ .reg .u64 t; cvta.to.shared.u64 t, %1; cvt.u32.u64 %0, t; }" : "=r"(a) : "l"(p));
    return a;
}
__device__ __forceinline__ uint32_t lds32(uint32_t a) {
    uint32_t v;
    asm volatile("ld.shared.b32 %0, [%1];" : "=r"(v) : "r"(a));
    return v;
}
__device__ __forceinline__ void sts128(uint32_t a, uint32_t x, uint32_t y,
                                       uint32_t z, uint32_t w) {
    asm volatile("st.shared.v4.b32 [%0], {%1,%2,%3,%4};"
                 :: "r"(a), "r"(x), "r"(y), "r"(z), "r"(w) : "memory");
}
__device__ __forceinline__ uint32_t cvt_tf32(float x) {
    uint32_t r;
    asm("cvt.rna.tf32.f32 %0, %1;" : "=r"(r) : "f"(x));
    return r;
}
#define MMAT32(d, a, b) \
    asm volatile("mma.sync.aligned.m16n8k8.row.col.f32.tf32.tf32.f32 " \
        "{%0,%1,%2,%3},{%4,%5,%6,%7},{%8,%9},{%0,%1,%2,%3};" \
        : "+f"((d)[0]), "+f"((d)[1]), "+f"((d)[2]), "+f"((d)[3]) \
        : "r"((a)[0]), "r"((a)[1]), "r"((a)[2]), "r"((a)[3]), "r"((b)[0]), "r"((b)[1]))

#define PITCHB 144
#define PLSZ   18432
#define ENG_SMEM2 (8*PLSZ)

// convert one 128x32 fp32 tile -> 2 tf32 split planes in smem (sign/weight folded)
__device__ __forceinline__ void conv_tile2(uint32_t sa, int tbase,
                                           const float* __restrict__ src, int row0, int ld,
                                           int k0, const float* __restrict__ w, float sgn)
{
    int tid = threadIdx.x;
    uint32_t p0 = sa + tbase*PLSZ;
    uint32_t p1 = p0 + PLSZ;
    #pragma unroll
    for (int p = 0; p < 4; p++) {
        int idx = tid + p*256;
        int row = idx >> 3, c4 = idx & 7;
        float4 v = *(const float4*)(src + (size_t)(row0+row)*ld + k0 + c4*4);
        if (w) {
            float4 wv = *(const float4*)(w + k0 + c4*4);
            v.x *= wv.x; v.y *= wv.y; v.z *= wv.z; v.w *= wv.w;
        }
        v.x *= sgn; v.y *= sgn; v.z *= sgn; v.w *= sgn;
        uint32_t h0 = cvt_tf32(v.x), h1 = cvt_tf32(v.y);
        uint32_t h2 = cvt_tf32(v.z), h3 = cvt_tf32(v.w);
        uint32_t m0 = cvt_tf32(v.x - __uint_as_float(h0));
        uint32_t m1 = cvt_tf32(v.y - __uint_as_float(h1));
        uint32_t m2 = cvt_tf32(v.z - __uint_as_float(h2));
        uint32_t m3 = cvt_tf32(v.w - __uint_as_float(h3));
        uint32_t off = row*PITCHB + c4*16;
        sts128(p0 + off, h0, h1, h2, h3);
        sts128(p1 + off, m0, m1, m2, m3);
    }
}

// ============================================================================
// split-tf32 complex GEMM via mma.sync m16n8k8 (q-chain ONLY — G and GZt):
//   D[i,j] = sum_k P[i,k] * op(Q[j,k]) ; conj: op=conj, else identity.
//   128x128 tile per CTA; blockIdx.z = plane (bit0) + 2*kslice.
// ============================================================================
__global__ __launch_bounds__(256, 1)
void cgemm_mma(const float* __restrict__ Pre, const float* __restrict__ Pim, int ldp,
               const float* __restrict__ Qre, const float* __restrict__ Qim, int ldq,
               float* __restrict__ Cre, float* __restrict__ Cim, int ldc,
               int Kper, int conj, const float* __restrict__ w, int partElems)
{
    extern __shared__ char dsm[];
    uint32_t sa = smem_u32(dsm);
    int tid = threadIdx.x;
    int wid = tid >> 5, lane = tid & 31;
    int g = lane >> 2, t4 = lane & 3;
    int warpM = wid >> 2, warpN = wid & 3;
    int i0 = blockIdx.y * 128, j0 = blockIdx.x * 128;
    int plane = blockIdx.z & 1, ks = blockIdx.z >> 1;

    const float* A0 = (conj && plane) ? Pim : Pre;
    const float* A1 = (conj && plane) ? Pre : Pim;
    float s1 = ((conj && plane) || (!conj && !plane)) ? -1.f : 1.f;
    const float* B0 = (!conj && plane) ? Qim : Qre;
    const float* B1 = (!conj && plane) ? Qre : Qim;

    float acc[4][4][4] = {};

    int nCh = Kper >> 5;
    for (int ch = 0; ch < nCh; ch++) {
        int k0 = ks * Kper + ch * 32;
        conv_tile2(sa, 0, A0, i0, ldp, k0, w, 1.f);
        conv_tile2(sa, 2, A1, i0, ldp, k0, w, s1);
        conv_tile2(sa, 4, B0, j0, ldq, k0, (const float*)0, 1.f);
        conv_tile2(sa, 6, B1, j0, ldq, k0, (const float*)0, 1.f);
        __syncthreads();

        const int ta[6] = {0, 0, 1, 2, 2, 3};
        const int tb[6] = {4, 5, 4, 6, 7, 6};
        #pragma unroll
        for (int ps = 0; ps < 6; ps++) {
            uint32_t ab = sa + ta[ps]*PLSZ;
            uint32_t bb = sa + tb[ps]*PLSZ;
            #pragma unroll
            for (int kk = 0; kk < 4; kk++) {
                uint32_t afr[4][4], bfr[4][2];
                #pragma unroll
                for (int am = 0; am < 4; am++) {
                    uint32_t r0 = ab + (warpM*64 + am*16 + g)*PITCHB + (kk*8 + t4)*4;
                    afr[am][0] = lds32(r0);
                    afr[am][1] = lds32(r0 + 8*PITCHB);
                    afr[am][2] = lds32(r0 + 16);
                    afr[am][3] = lds32(r0 + 8*PITCHB + 16);
                }
                #pragma unroll
                for (int bn = 0; bn < 4; bn++) {
                    uint32_t r0 = bb + (warpN*32 + bn*8 + g)*PITCHB + (kk*8 + t4)*4;
                    bfr[bn][0] = lds32(r0);
                    bfr[bn][1] = lds32(r0 + 16);
                }
                #pragma unroll
                for (int am = 0; am < 4; am++)
                    #pragma unroll
                    for (int bn = 0; bn < 4; bn++)
                        MMAT32(acc[am][bn], afr[am], bfr[bn]);
            }
        }
        __syncthreads();
    }

    float* dst = plane ? Cim : Cre;
    size_t zoff = (size_t)ks * partElems;
    #pragma unroll
    for (int am = 0; am < 4; am++) {
        #pragma unroll
        for (int bn = 0; bn < 4; bn++) {
            int r = i0 + warpM*64 + am*16 + g;
            int c = j0 + warpN*32 + bn*8 + 2*t4;
            float2 v0 = make_float2(acc[am][bn][0], acc[am][bn][1]);
            float2 v1 = make_float2(acc[am][bn][2], acc[am][bn][3]);
            *(float2*)(dst + zoff + (size_t)r*ldc + c) = v0;
            *(float2*)(dst + zoff + (size_t)(r+8)*ldc + c) = v1;
        }
    }
}

// ---------------- fp32 csyrk: C = (A*diag(w)) @ A^H partials ----------------
// launch_bounds(256,2): occupancy-only change; per-element FP order unchanged.
__global__ __launch_bounds__(256, 2)
void csyrk_part(float* __restrict__ Pre, float* __restrict__ Pim,
                const float* __restrict__ Are, const float* __restrict__ Aim,
                const float* __restrict__ w, int lda, int kChunk)
{
    const int BM = 64, BN = 64, BK = 32, TM = 4, TN = 4;
    __shared__ float as_re[BK][BM+1], as_im[BK][BM+1];
    __shared__ float bs_re[BK][BN+1], bs_im[BK][BN+1];
    int i0 = blockIdx.y * BM, j0 = blockIdx.x * BN;
    int k0 = blockIdx.z * kChunk;
    int t  = threadIdx.x;
    int tx = t & 15, ty = t >> 4;
    float cre[TM][TN] = {}, cim[TM][TN] = {};

    for (int kb = 0; kb < kChunk; kb += BK) {
        #pragma unroll
        for (int e = t; e < BM*BK; e += 256) {
            int row = e >> 5, kk = e & 31;
            int g = (i0 + row) * lda + k0 + kb + kk;
            float ww = w ? w[k0 + kb + kk] : 1.0f;
            as_re[kk][row] = Are[g] * ww;
            as_im[kk][row] = Aim[g] * ww;
        }
        #pragma unroll
        for (int e = t; e < BN*BK; e += 256) {
            int col = e >> 5, kk = e & 31;
            int g = (j0 + col) * lda + k0 + kb + kk;
            bs_re[kk][col] = Are[g];
            bs_im[kk][col] = Aim[g];
        }
        __syncthreads();
        #pragma unroll 4
        for (int kk = 0; kk < BK; kk++) {
            float ar[TM], ai[TM], br[TN], bi[TN];
            #pragma unroll
            for (int i = 0; i < TM; i++) { ar[i] = as_re[kk][ty*TM+i]; ai[i] = as_im[kk][ty*TM+i]; }
            #pragma unroll
            for (int j = 0; j < TN; j++) { br[j] = bs_re[kk][tx*TN+j]; bi[j] = bs_im[kk][tx*TN+j]; }
            #pragma unroll
            for (int i = 0; i < TM; i++)
                #pragma unroll
                for (int j = 0; j < TN; j++) {
                    cre[i][j] += ar[i]*br[j];
                    cre[i][j] += ai[i]*bi[j];
                    cim[i][j] += ai[i]*br[j];
                    cim[i][j] -= ar[i]*bi[j];
                }
        }
        __syncthreads();
    }
    size_t off = (size_t)blockIdx.z * (Mdim * Mdim);
    #pragma unroll
    for (int i = 0; i < TM; i++)
        #pragma unroll
        for (int j = 0; j < TN; j++) {
            int gi = i0 + ty*TM + i, gj = j0 + tx*TN + j;
            Pre[off + gi*Mdim + gj] = cre[i][j];
            Pim[off + gi*Mdim + gj] = cim[i][j];
        }
}

// ---------------- proven fp32 SIMT complex NN GEMM (d-chain: Newton + Zt) ----------------
// launch_bounds(256,2): occupancy-only; bit-exact per element.
template<int BM, int BN, int BK, int TM, int TN>
__global__ __launch_bounds__(256, 2)
void cgemm_nn(float* __restrict__ Cre, float* __restrict__ Cim,
              const float* __restrict__ Are, const float* __restrict__ Aim, int lda,
              const float* __restrict__ Bre, const float* __restrict__ Bim, int ldb,
              int kChunk, int MNpart)
{
    __shared__ float as_re[BK][BM+1], as_im[BK][BM+1];
    __shared__ float bs_re[BK][BN+1], bs_im[BK][BN+1];
    int i0 = blockIdx.y * BM, j0 = blockIdx.x * BN;
    int k0 = blockIdx.z * kChunk;
    int t  = threadIdx.x;
    int tx = t % (BN/TN), ty = t / (BN/TN);
    float cre[TM][TN] = {}, cim[TM][TN] = {};

    for (int kb = 0; kb < kChunk; kb += BK) {
        #pragma unroll
        for (int e = t; e < BM*BK; e += 256) {
            int row = e / BK, kk = e % BK;
            int g = (i0 + row) * lda + k0 + kb + kk;
            as_re[kk][row] = Are[g];
            as_im[kk][row] = Aim[g];
        }
        #pragma unroll
        for (int e = t; e < BK*BN; e += 256) {
            int kk = e / BN, col = e % BN;
            int g = (k0 + kb + kk) * ldb + j0 + col;
            bs_re[kk][col] = Bre[g];
            bs_im[kk][col] = Bim[g];
        }
        __syncthreads();
        #pragma unroll 4
        for (int kk = 0; kk < BK; kk++) {
            float ar[TM], ai[TM], br[TN], bi[TN];
            #pragma unroll
            for (int i = 0; i < TM; i++) { ar[i] = as_re[kk][ty*TM+i]; ai[i] = as_im[kk][ty*TM+i]; }
            #pragma unroll
            for (int j = 0; j < TN; j++) { br[j] = bs_re[kk][tx*TN+j]; bi[j] = bs_im[kk][tx*TN+j]; }
            #pragma unroll
            for (int i = 0; i < TM; i++)
                #pragma unroll
                for (int j = 0; j < TN; j++) {
                    cre[i][j] += ar[i]*br[j];
                    cre[i][j] -= ai[i]*bi[j];
                    cim[i][j] += ar[i]*bi[j];
                    cim[i][j] += ai[i]*br[j];
                }
        }
        __syncthreads();
    }
    size_t off = (size_t)blockIdx.z * MNpart;
    #pragma unroll
    for (int i = 0; i < TM; i++)
        #pragma unroll
        for (int j = 0; j < TN; j++) {
            int gi = i0 + ty*TM + i, gj = j0 + tx*TN + j;
            Cre[off + (size_t)gi*ldb + gj] = cre[i][j];
            Cim[off + (size_t)gi*ldb + gj] = cim[i][j];
        }
}

// ---------------- reduces ----------------
__global__ void reduce_RG(float* __restrict__ Cre, float* __restrict__ Cim, int SK, int ridge) {
    int e = blockIdx.x * 256 + threadIdx.x;
    float sr = 0.f, si = 0.f;
    for (int z = 0; z < SK; z++) { sr += g_part_re[z*65536 + e]; si += g_part_im[z*65536 + e]; }
    if (ridge && (e >> 8) == (e & 255)) sr += 0.01f;
    Cre[e] = sr; Cim[e] = si;
}
__global__ void reduce_sum(float* __restrict__ Cre, float* __restrict__ Cim, int SK) {
    int e = blockIdx.x * 256 + threadIdx.x;
    float sr = 0.f, si = 0.f;
    for (int z = 0; z < SK; z++) { sr += g_part_re[z*65536 + e]; si += g_part_im[z*65536 + e]; }
    Cre[e] = sr; Cim[e] = si;
}
__global__ void reduce_newton(float* __restrict__ Xnre, float* __restrict__ Xnim,
                              const float* __restrict__ Xre, const float* __restrict__ Xim, int SK)
{
    int e = blockIdx.x * 256 + threadIdx.x;
    float sr = 0.f, si = 0.f;
    for (int z = 0; z < SK; z++) { sr += g_part_re[z*65536 + e]; si += g_part_im[z*65536 + e]; }
    Xnre[e] = 2.f*Xre[e] - sr;
    Xnim[e] = 2.f*Xim[e] - si;
}

// ---------------- alpha = tr(R)/||R||_F^2 ; X0 = alpha*I ----------------
__global__ void trace_alpha() {
    __shared__ float red[1024];
    __shared__ float s_fro;
    int t = threadIdx.x;
    float fro = 0.f;
    for (int e = t; e < 65536; e += 1024) {
        float a = g_Rre[e], b = g_Rim[e];
        fro += a*a + b*b;
    }
    red[t] = fro; __syncthreads();
    for (int o = 512; o > 0; o >>= 1) { if (t < o) red[t] += red[t+o]; __syncthreads(); }
    if (t == 0) s_fro = red[0];
    __syncthreads();
    float tr = 0.f;
    for (int i = t; i < 256; i += 1024) tr += g_Rre[i*257];
    red[t] = tr; __syncthreads();
    for (int o = 512; o > 0; o >>= 1) { if (t < o) red[t] += red[t+o]; __syncthreads(); }
    if (t == 0) g_scal[0] = red[0] / s_fro;
}
__global__ void init_X0(float* __restrict__ Xre, float* __restrict__ Xim) {
    int i = blockIdx.x, j = threadIdx.x;
    float a = g_scal[0];
    Xre[i*Mdim + j] = (i == j) ? a : 0.f;
    Xim[i*Mdim + j] = 0.f;
}

// ---------------- Bc = conj(symmetrize(Rinv))  (round-8 exact) ----------------
__global__ void symm_conj(const float* __restrict__ Xre, const float* __restrict__ Xim,
                          float* __restrict__ Bre, float* __restrict__ Bim) {
    int e = blockIdx.x * 256 + threadIdx.x;
    int i = e >> 8, j = e & 255;
    Bre[e] = 0.5f * (Xre[i*256 + j] + Xre[j*256 + i]);
    Bim[e] = 0.5f * (Xim[j*256 + i] - Xim[i*256 + j]);
}

// ---------------- transpose A -> At [L][M] ----------------
__global__ void transposeA(const float* __restrict__ Are, const float* __restrict__ Aim) {
    __shared__ float t0[32][33], t1[32][33];
    int lb = blockIdx.x * 32, mb = blockIdx.y * 32;
    int x = threadIdx.x, y = threadIdx.y;
    for (int yy = y; yy < 32; yy += 8) {
        t0[yy][x] = Are[(size_t)(mb+yy)*Ldim + lb + x];
        t1[yy][x] = Aim[(size_t)(mb+yy)*Ldim + lb + x];
    }
    __syncthreads();
    for (int yy = y; yy < 32; yy += 8) {
        g_Atre[(size_t)(lb+yy)*Mdim + mb + x] = t0[x][yy];
        g_Atim[(size_t)(lb+yy)*Mdim + mb + x] = t1[x][yy];
    }
}

// ---------------- q, d, v, u (transposed layout) ----------------
__global__ __launch_bounds__(256)
void qduv_kernel(const float* __restrict__ gamma, const float* __restrict__ delta) {
    int wid = threadIdx.x >> 5, lane = threadIdx.x & 31;
    int l = blockIdx.x * 8 + wid;
    const float4* zr  = (const float4*)(g_Ztre + (size_t)l*Mdim);
    const float4* zi  = (const float4*)(g_Ztim + (size_t)l*Mdim);
    const float4* gr  = (const float4*)(g_GZre + (size_t)l*Mdim);
    const float4* gi  = (const float4*)(g_GZim + (size_t)l*Mdim);
    const float4* ar  = (const float4*)(g_Atre + (size_t)l*Mdim);
    const float4* ai  = (const float4*)(g_Atim + (size_t)l*Mdim);
    float q = 0.f, d = 0.f;
    #pragma unroll
    for (int it = 0; it < 2; it++) {
        int k = lane + it*32;
        float4 a = zr[k], b = zi[k], c = gr[k], e = gi[k], f = ar[k], g2 = ai[k];
        q += a.x*c.x + a.y*c.y + a.z*c.z + a.w*c.w
           + b.x*e.x + b.y*e.y + b.z*e.z + b.w*e.w;
        d += a.x*f.x + a.y*f.y + a.z*f.z + a.w*f.w
           - (b.x*g2.x + b.y*g2.y + b.z*g2.z + b.w*g2.w);
    }
    q = warp_sum(q); d = warp_sum(d);
    if (lane == 0) {
        float v = q / (d + 1e-12f);
        float dl = 1.f / (1.f + expf(-delta[0]));
        float p = gamma[l];
        g_v[l] = v;
        g_u[l] = p + dl * (v - p);
    }
}

// ---------------- LayerNorm + kv stats ----------------
__global__ void ln_kernel(const float* __restrict__ ln_w, const float* __restrict__ ln_b,
                          const float* __restrict__ in_w, const float* __restrict__ in_b)
{
    __shared__ float red[512];
    __shared__ float s_mu, s_inv;
    int t = threadIdx.x;
    float s = 0.f;
    for (int i = t; i < Ldim; i += 512) s += g_u[i];
    red[t] = s; __syncthreads();
    for (int o = 256; o > 0; o >>= 1) { if (t < o) red[t] += red[t+o]; __syncthreads(); }
    if (t == 0) s_mu = red[0] / (float)Ldim;
    __syncthreads();
    float mu = s_mu, s2 = 0.f;
    for (int i = t; i < Ldim; i += 512) { float d = g_u[i] - mu; s2 += d*d; }
    red[t] = s2; __syncthreads();
    for (int o = 256; o > 0; o >>= 1) { if (t < o) red[t] += red[t+o]; __syncthreads(); }
    if (t == 0) s_inv = rsqrtf(red[0] / (float)Ldim + 1e-5f);
    __syncthreads();
    float inv = s_inv;
    float w1 = in_w[1], b1 = in_b[1];
    float kmin = 3.4e38f, kmax = -3.4e38f;
    for (int i = t; i < Ldim; i += 512) {
        float up = (g_u[i] - mu) * inv * ln_w[i] + ln_b[i];
        g_up[i] = up;
        float k2 = (up * w1 + b1) * LOG2E_F;
        kmin = fminf(kmin, k2); kmax = fmaxf(kmax, k2);
    }
    red[t] = kmax; __syncthreads();
    for (int o = 256; o > 0; o >>= 1) { if (t < o) red[t] = fmaxf(red[t], red[t+o]); __syncthreads(); }
    if (t == 0) g_scal[2] = red[0];
    __syncthreads();
    red[t] = kmin; __syncthreads();
    for (int o = 256; o > 0; o >>= 1) { if (t < o) red[t] = fminf(red[t], red[t+o]); __syncthreads(); }
    if (t == 0) g_scal[1] = red[0];
}

// ---------------- attention (rank-1 softmax) ----------------
__global__ __launch_bounds__(256)
void attn_kernel(const float* __restrict__ in_w, const float* __restrict__ in_b,
                 const float* __restrict__ out_w, const float* __restrict__ out_b)
{
    __shared__ float skv2[Ldim];
    __shared__ float svv[Ldim];
    int t = threadIdx.x;
    float w0 = in_w[0], b0 = in_b[0];
    float w1 = in_w[1], b1 = in_b[1];
    float w2 = in_w[2], b2 = in_b[2];
    for (int j = t; j < Ldim; j += 256) {
        float up = g_up[j];
        skv2[j] = (up * w1 + b1) * LOG2E_F;
        svv[j]  = up * w2 + b2;
    }
    __syncthreads();
    float k2min = g_scal[1], k2max = g_scal[2];
    float ow = out_w[0], ob = out_b[0];
    int warp = t >> 5, lane = t & 31;
    #pragma unroll
    for (int r = 0; r < 4; r++) {
        int i = blockIdx.x * 32 + warp * 4 + r;
        float qv = g_up[i] * w0 + b0;
        float m2 = (qv >= 0.f) ? qv * k2max : qv * k2min;
        float den = 0.f, num = 0.f;
        for (int j = lane; j < Ldim; j += 32) {
            float arg = qv * skv2[j] - m2;
            float e;
            asm("ex2.approx.f32 %0, %1;" : "=f"(e) : "f"(arg));
            den += e;
            num = fmaf(e, svv[j], num);
        }
        den = warp_sum(den); num = warp_sum(num);
        if (lane == 0) g_attn[i] = (num / den) * ow + ob;
    }
}

// ---------------- gate matvec + final fuse ----------------
__global__ __launch_bounds__(256)
void final_kernel(const float* __restrict__ W, const float* __restrict__ gb,
                  const float* __restrict__ gamma, const float* __restrict__ lmbda,
                  float* __restrict__ out)
{
    int warp = threadIdx.x >> 5, lane = threadIdx.x & 31;
    int i = blockIdx.x * 8 + warp;
    const float4* Wr = (const float4*)(W + (size_t)i * Ldim);
    const float4* U4 = (const float4*)g_u;
    float acc = 0.f;
    for (int k = lane; k < Ldim/4; k += 32) {
        float4 w4 = Wr[k]; float4 u4 = U4[k];
        acc += w4.x*u4.x + w4.y*u4.y + w4.z*u4.z + w4.w*u4.w;
    }
    acc = warp_sum(acc);
    if (lane == 0) {
        float z = acc + gb[i];
        float g = 1.f / (1.f + expf(-z));
        float s = g * g_v[i] + (1.f - g) * gamma[i] + g_attn[i] - lmbda[0];
        out[i] = fmaxf(s, 0.f);
    }
}

// ---------------- launch (round-8 sequence exactly) ----------------
extern "C" void kernel_launch(void* const* d_in, const int* in_sizes, int n_in,
                              void* d_out, int out_size)
{
    const float* gamma  = (const float*)d_in[0];
    const float* A_re   = (const float*)d_in[1];
    const float* A_im   = (const float*)d_in[2];
    const float* X_re   = (const float*)d_in[3];
    const float* X_im   = (const float*)d_in[4];
    const float* ln_w   = (const float*)d_in[5];
    const float* ln_b   = (const float*)d_in[6];
    const float* in_w   = (const float*)d_in[7];
    const float* in_b   = (const float*)d_in[8];
    const float* out_w  = (const float*)d_in[9];
    const float* out_b  = (const float*)d_in[10];
    const float* gate_W = (const float*)d_in[11];
    const float* gate_b = (const float*)d_in[12];
    const float* delta  = (const float*)d_in[13];
    const float* lmbda  = (const float*)d_in[14];
    float* out = (float*)d_out;

    cudaFuncSetAttribute(cgemm_mma, cudaFuncAttributeMaxDynamicSharedMemorySize, ENG_SMEM2);

    float *Rre,*Rim,*Gre,*Gim,*Xare,*Xaim,*Xbre,*Xbim,*Pre,*Pim;
    float *pre,*pim,*Atre,*Atim,*Ztre,*Ztim,*GZre,*GZim;
    cudaGetSymbolAddress((void**)&Rre,  g_Rre);   cudaGetSymbolAddress((void**)&Rim,  g_Rim);
    cudaGetSymbolAddress((void**)&Gre,  g_Gre);   cudaGetSymbolAddress((void**)&Gim,  g_Gim);
    cudaGetSymbolAddress((void**)&Xare, g_Xa_re); cudaGetSymbolAddress((void**)&Xaim, g_Xa_im);
    cudaGetSymbolAddress((void**)&Xbre, g_Xb_re); cudaGetSymbolAddress((void**)&Xbim, g_Xb_im);
    cudaGetSymbolAddress((void**)&Pre,  g_P_re);  cudaGetSymbolAddress((void**)&Pim,  g_P_im);
    cudaGetSymbolAddress((void**)&pre,  g_part_re); cudaGetSymbolAddress((void**)&pim, g_part_im);
    cudaGetSymbolAddress((void**)&Atre, g_Atre);  cudaGetSymbolAddress((void**)&Atim, g_Atim);
    cudaGetSymbolAddress((void**)&Ztre, g_Ztre);  cudaGetSymbolAddress((void**)&Ztim, g_Ztim);
    cudaGetSymbolAddress((void**)&GZre, g_GZre);  cudaGetSymbolAddress((void**)&GZim, g_GZim);

    // At = A^T (planar)
    transposeA<<<dim3(128, 8), dim3(32, 8)>>>(A_re, A_im);

    // R = (A*diag(gamma)) A^H + ridge I : fp32 csyrk, 32-way k-split (round-8 exact)
    csyrk_part<<<dim3(4,4,32), 256>>>(pre, pim, A_re, A_im, gamma, Ldim, 128);
    reduce_RG<<<256, 256>>>(Rre, Rim, 32, 1);

    // G = X X^H : 2-split conj MMA (q-chain), 16-way k-split (round-8 exact)
    cgemm_mma<<<dim3(2,2,32), 256, ENG_SMEM2>>>(X_re, X_im, Tdim, X_re, X_im, Tdim,
                                                pre, pim, Mdim, 128, 1, nullptr, 65536);
    reduce_RG<<<256, 256>>>(Gre, Gim, 16, 0);

    // alpha and X0 = alpha*I
    trace_alpha<<<1, 1024>>>();
    init_X0<<<256, 256>>>(Xare, Xaim);

    // order-2 Newton (fp32 SIMT): Xn = 2X - X(RX), 7 iterations (round-8 exact)
    float *Xc_re = Xare, *Xc_im = Xaim, *Xn_re = Xbre, *Xn_im = Xbim;
    for (int it = 0; it < 7; ++it) {
        cgemm_nn<64,64,32,4,4><<<dim3(4,4,8), 256>>>(pre, pim, Rre, Rim, Mdim,
                                                     Xc_re, Xc_im, Mdim, 32, 65536);
        reduce_sum<<<256, 256>>>(Pre, Pim, 8);
        cgemm_nn<64,64,32,4,4><<<dim3(4,4,8), 256>>>(pre, pim, Xc_re, Xc_im, Mdim,
                                                     Pre, Pim, Mdim, 32, 65536);
        reduce_newton<<<256, 256>>>(Xn_re, Xn_im, Xc_re, Xc_im, 8);
        float* tmp;
        tmp = Xc_re; Xc_re = Xn_re; Xn_re = tmp;
        tmp = Xc_im; Xc_im = Xn_im; Xn_im = tmp;
    }

    // Bc = conj(symmetrized Rinv)  (round-8 exact)
    symm_conj<<<256, 256>>>(Xc_re, Xc_im, Pre, Pim);

    // Zt[l,m] = sum_k At[l,k] * Bc[k,m]   (fp32 SIMT NN — d-chain precision, round-8 exact)
    cgemm_nn<64,64,32,4,4><<<dim3(4,64,1), 256>>>(Ztre, Ztim, Atre, Atim, Mdim,
                                                  Pre, Pim, Mdim, 256, 0);

    // GZt[l,m] = sum_k Zt[l,k] * G[m,k]   (2-split MMA, q-chain, round-8 exact)
    cgemm_mma<<<dim3(2,32,2), 256, ENG_SMEM2>>>(Ztre, Ztim, Mdim, Gre, Gim, Mdim,
                                                GZre, GZim, Mdim, 256, 0, nullptr, 0);

    qduv_kernel<<<512, 256>>>(gamma, delta);
    ln_kernel<<<1, 512>>>(ln_w, ln_b, in_w, in_b);
    attn_kernel<<<128, 256>>>(in_w, in_b, out_w, out_b);
    final_kernel<<<512, 256>>>(gate_W, gate_b, gamma, lmbda, out);
}

// round 13
// speedup vs baseline: 1.4299x; 1.0810x over previous
#include <cuda_runtime.h>
#include <cuda_bf16.h>
#include <math.h>
#include <stdint.h>

#define Mdim 256
#define Ldim 4096
#define Tdim 2048
#define LOG2E_F 1.4426950408889634f

// ---------------- device scratch ----------------
__device__ float g_Rre[Mdim*Mdim], g_Rim[Mdim*Mdim];
__device__ float g_Gre[Mdim*Mdim], g_Gim[Mdim*Mdim];
__device__ float g_Xa_re[Mdim*Mdim], g_Xa_im[Mdim*Mdim];
__device__ float g_Xb_re[Mdim*Mdim], g_Xb_im[Mdim*Mdim];
__device__ float g_P_re[Mdim*Mdim],  g_P_im[Mdim*Mdim];
__device__ float g_part_re[32*Mdim*Mdim], g_part_im[32*Mdim*Mdim];
__device__ float g_Atre[Ldim*Mdim], g_Atim[Ldim*Mdim];
__device__ float g_Ztre[Ldim*Mdim], g_Ztim[Ldim*Mdim];
__device__ float g_GZre[Ldim*Mdim], g_GZim[Ldim*Mdim];
__device__ float g_v[Ldim], g_u[Ldim], g_up[Ldim], g_attn[Ldim];
__device__ float g_scal[4];   // [0]=alpha  [1]=kv2min [2]=kv2max

__device__ __forceinline__ float warp_sum(float v) {
    #pragma unroll
    for (int o = 16; o > 0; o >>= 1) v += __shfl_xor_sync(0xffffffffu, v, o);
    return v;
}

// ---------------- smem helpers ----------------
__device__ __forceinline__ uint32_t smem_u32(const void* p) {
    uint32_t a;
    asm("{ .reg .u64 t; cvta.to.shared.u64 t, %1; cvt.u32.u64 %0, t; }" : "=r"(a) : "l"(p));
    return a;
}
__device__ __forceinline__ uint32_t lds32(uint32_t a) {
    uint32_t v;
    asm volatile("ld.shared.b32 %0, [%1];" : "=r"(v) : "r"(a));
    return v;
}
__device__ __forceinline__ void sts128(uint32_t a, uint32_t x, uint32_t y,
                                       uint32_t z, uint32_t w) {
    asm volatile("st.shared.v4.b32 [%0], {%1,%2,%3,%4};"
                 :: "r"(a), "r"(x), "r"(y), "r"(z), "r"(w) : "memory");
}
__device__ __forceinline__ uint32_t cvt_tf32(float x) {
    uint32_t r;
    asm("cvt.rna.tf32.f32 %0, %1;" : "=r"(r) : "f"(x));
    return r;
}
#define MMAT32(d, a, b) \
    asm volatile("mma.sync.aligned.m16n8k8.row.col.f32.tf32.tf32.f32 " \
        "{%0,%1,%2,%3},{%4,%5,%6,%7},{%8,%9},{%0,%1,%2,%3};" \
        : "+f"((d)[0]), "+f"((d)[1]), "+f"((d)[2]), "+f"((d)[3]) \
        : "r"((a)[0]), "r"((a)[1]), "r"((a)[2]), "r"((a)[3]), "r"((b)[0]), "r"((b)[1]))

#define PITCHB 144
#define PLSZ   18432
#define ENG_SMEM2 (8*PLSZ)

// convert one 128x32 fp32 tile -> 2 tf32 split planes in smem (sign/weight folded)
__device__ __forceinline__ void conv_tile2(uint32_t sa, int tbase,
                                           const float* __restrict__ src, int row0, int ld,
                                           int k0, const float* __restrict__ w, float sgn)
{
    int tid = threadIdx.x;
    uint32_t p0 = sa + tbase*PLSZ;
    uint32_t p1 = p0 + PLSZ;
    #pragma unroll
    for (int p = 0; p < 4; p++) {
        int idx = tid + p*256;
        int row = idx >> 3, c4 = idx & 7;
        float4 v = *(const float4*)(src + (size_t)(row0+row)*ld + k0 + c4*4);
        if (w) {
            float4 wv = *(const float4*)(w + k0 + c4*4);
            v.x *= wv.x; v.y *= wv.y; v.z *= wv.z; v.w *= wv.w;
        }
        v.x *= sgn; v.y *= sgn; v.z *= sgn; v.w *= sgn;
        uint32_t h0 = cvt_tf32(v.x), h1 = cvt_tf32(v.y);
        uint32_t h2 = cvt_tf32(v.z), h3 = cvt_tf32(v.w);
        uint32_t m0 = cvt_tf32(v.x - __uint_as_float(h0));
        uint32_t m1 = cvt_tf32(v.y - __uint_as_float(h1));
        uint32_t m2 = cvt_tf32(v.z - __uint_as_float(h2));
        uint32_t m3 = cvt_tf32(v.w - __uint_as_float(h3));
        uint32_t off = row*PITCHB + c4*16;
        sts128(p0 + off, h0, h1, h2, h3);
        sts128(p1 + off, m0, m1, m2, m3);
    }
}

// ============================================================================
// split-tf32 complex GEMM via mma.sync m16n8k8 (q-chain ONLY — G and GZt)
// ============================================================================
__global__ __launch_bounds__(256, 1)
void cgemm_mma(const float* __restrict__ Pre, const float* __restrict__ Pim, int ldp,
               const float* __restrict__ Qre, const float* __restrict__ Qim, int ldq,
               float* __restrict__ Cre, float* __restrict__ Cim, int ldc,
               int Kper, int conj, const float* __restrict__ w, int partElems)
{
    extern __shared__ char dsm[];
    uint32_t sa = smem_u32(dsm);
    int tid = threadIdx.x;
    int wid = tid >> 5, lane = tid & 31;
    int g = lane >> 2, t4 = lane & 3;
    int warpM = wid >> 2, warpN = wid & 3;
    int i0 = blockIdx.y * 128, j0 = blockIdx.x * 128;
    int plane = blockIdx.z & 1, ks = blockIdx.z >> 1;

    const float* A0 = (conj && plane) ? Pim : Pre;
    const float* A1 = (conj && plane) ? Pre : Pim;
    float s1 = ((conj && plane) || (!conj && !plane)) ? -1.f : 1.f;
    const float* B0 = (!conj && plane) ? Qim : Qre;
    const float* B1 = (!conj && plane) ? Qre : Qim;

    float acc[4][4][4] = {};

    int nCh = Kper >> 5;
    for (int ch = 0; ch < nCh; ch++) {
        int k0 = ks * Kper + ch * 32;
        conv_tile2(sa, 0, A0, i0, ldp, k0, w, 1.f);
        conv_tile2(sa, 2, A1, i0, ldp, k0, w, s1);
        conv_tile2(sa, 4, B0, j0, ldq, k0, (const float*)0, 1.f);
        conv_tile2(sa, 6, B1, j0, ldq, k0, (const float*)0, 1.f);
        __syncthreads();

        const int ta[6] = {0, 0, 1, 2, 2, 3};
        const int tb[6] = {4, 5, 4, 6, 7, 6};
        #pragma unroll
        for (int ps = 0; ps < 6; ps++) {
            uint32_t ab = sa + ta[ps]*PLSZ;
            uint32_t bb = sa + tb[ps]*PLSZ;
            #pragma unroll
            for (int kk = 0; kk < 4; kk++) {
                uint32_t afr[4][4], bfr[4][2];
                #pragma unroll
                for (int am = 0; am < 4; am++) {
                    uint32_t r0 = ab + (warpM*64 + am*16 + g)*PITCHB + (kk*8 + t4)*4;
                    afr[am][0] = lds32(r0);
                    afr[am][1] = lds32(r0 + 8*PITCHB);
                    afr[am][2] = lds32(r0 + 16);
                    afr[am][3] = lds32(r0 + 8*PITCHB + 16);
                }
                #pragma unroll
                for (int bn = 0; bn < 4; bn++) {
                    uint32_t r0 = bb + (warpN*32 + bn*8 + g)*PITCHB + (kk*8 + t4)*4;
                    bfr[bn][0] = lds32(r0);
                    bfr[bn][1] = lds32(r0 + 16);
                }
                #pragma unroll
                for (int am = 0; am < 4; am++)
                    #pragma unroll
                    for (int bn = 0; bn < 4; bn++)
                        MMAT32(acc[am][bn], afr[am], bfr[bn]);
            }
        }
        __syncthreads();
    }

    float* dst = plane ? Cim : Cre;
    size_t zoff = (size_t)ks * partElems;
    #pragma unroll
    for (int am = 0; am < 4; am++) {
        #pragma unroll
        for (int bn = 0; bn < 4; bn++) {
            int r = i0 + warpM*64 + am*16 + g;
            int c = j0 + warpN*32 + bn*8 + 2*t4;
            float2 v0 = make_float2(acc[am][bn][0], acc[am][bn][1]);
            float2 v1 = make_float2(acc[am][bn][2], acc[am][bn][3]);
            *(float2*)(dst + zoff + (size_t)r*ldc + c) = v0;
            *(float2*)(dst + zoff + (size_t)(r+8)*ldc + c) = v1;
        }
    }
}

// ============================================================================
// High-ILP fp32 SIMT complex GEMMs: BM=128, BN=64, BK=16, TM=8, TN=4.
// 6x LDS.128 per 128 FFMA in the inner iteration.
// ============================================================================
#define BBM 128
#define BBN 64
#define BBK 16

// conj variant (csyrk): C[i,j] = sum_k (w[k]*A[i,k]) * conj(A[j,k])
__global__ __launch_bounds__(256)
void csyrk_big(float* __restrict__ Pre, float* __restrict__ Pim,
               const float* __restrict__ Are, const float* __restrict__ Aim,
               const float* __restrict__ w, int lda, int kChunk)
{
    __shared__ float as_re[BBK][BBM+4], as_im[BBK][BBM+4];
    __shared__ float bs_re[BBK][BBN+4], bs_im[BBK][BBN+4];
    int i0 = blockIdx.y * BBM, j0 = blockIdx.x * BBN;
    int k0 = blockIdx.z * kChunk;
    int t  = threadIdx.x;
    int tx = t & 15, ty = t >> 4;
    int arow = t >> 2, ak4 = (t & 3) * 4;
    float cre[8][4] = {}, cim[8][4] = {};

    for (int kb = 0; kb < kChunk; kb += BBK) {
        int kbase = k0 + kb;
        float4 wv;
        if (w) wv = *(const float4*)(w + kbase + ak4);
        else   wv = make_float4(1.f, 1.f, 1.f, 1.f);
        #pragma unroll
        for (int r = 0; r < 2; r++) {
            int row = arow + r*64;
            float4 vr = *(const float4*)(Are + (size_t)(i0+row)*lda + kbase + ak4);
            float4 vi = *(const float4*)(Aim + (size_t)(i0+row)*lda + kbase + ak4);
            as_re[ak4+0][row] = vr.x*wv.x; as_re[ak4+1][row] = vr.y*wv.y;
            as_re[ak4+2][row] = vr.z*wv.z; as_re[ak4+3][row] = vr.w*wv.w;
            as_im[ak4+0][row] = vi.x*wv.x; as_im[ak4+1][row] = vi.y*wv.y;
            as_im[ak4+2][row] = vi.z*wv.z; as_im[ak4+3][row] = vi.w*wv.w;
        }
        {
            int col = t >> 2;
            float4 vr = *(const float4*)(Are + (size_t)(j0+col)*lda + kbase + ak4);
            float4 vi = *(const float4*)(Aim + (size_t)(j0+col)*lda + kbase + ak4);
            bs_re[ak4+0][col] = vr.x; bs_re[ak4+1][col] = vr.y;
            bs_re[ak4+2][col] = vr.z; bs_re[ak4+3][col] = vr.w;
            bs_im[ak4+0][col] = vi.x; bs_im[ak4+1][col] = vi.y;
            bs_im[ak4+2][col] = vi.z; bs_im[ak4+3][col] = vi.w;
        }
        __syncthreads();
        #pragma unroll
        for (int kk = 0; kk < BBK; kk++) {
            float ar[8], ai[8], br[4], bi[4];
            #pragma unroll
            for (int i = 0; i < 8; i++) { ar[i] = as_re[kk][ty*8+i]; ai[i] = as_im[kk][ty*8+i]; }
            #pragma unroll
            for (int j = 0; j < 4; j++) { br[j] = bs_re[kk][tx*4+j]; bi[j] = bs_im[kk][tx*4+j]; }
            #pragma unroll
            for (int i = 0; i < 8; i++)
                #pragma unroll
                for (int j = 0; j < 4; j++) {
                    cre[i][j] += ar[i]*br[j];
                    cre[i][j] += ai[i]*bi[j];
                    cim[i][j] += ai[i]*br[j];
                    cim[i][j] -= ar[i]*bi[j];
                }
        }
        __syncthreads();
    }
    size_t off = (size_t)blockIdx.z * (Mdim*Mdim);
    #pragma unroll
    for (int i = 0; i < 8; i++) {
        int gi = i0 + ty*8 + i, gj = j0 + tx*4;
        *(float4*)(Pre + off + (size_t)gi*Mdim + gj) = make_float4(cre[i][0], cre[i][1], cre[i][2], cre[i][3]);
        *(float4*)(Pim + off + (size_t)gi*Mdim + gj) = make_float4(cim[i][0], cim[i][1], cim[i][2], cim[i][3]);
    }
}

// nn variant: C[i,j] = sum_k A[i,k]*B[k,j]   (Newton + Zt; d-chain fp32)
__global__ __launch_bounds__(256)
void cgemm_big(float* __restrict__ Cre, float* __restrict__ Cim,
               const float* __restrict__ Are, const float* __restrict__ Aim, int lda,
               const float* __restrict__ Bre, const float* __restrict__ Bim, int ldb,
               int kChunk, int MNpart)
{
    __shared__ float as_re[BBK][BBM+4], as_im[BBK][BBM+4];
    __shared__ float bs_re[BBK][BBN+4], bs_im[BBK][BBN+4];
    int i0 = blockIdx.y * BBM, j0 = blockIdx.x * BBN;
    int k0 = blockIdx.z * kChunk;
    int t  = threadIdx.x;
    int tx = t & 15, ty = t >> 4;
    int arow = t >> 2, ak4 = (t & 3) * 4;
    int bk = t >> 4, bc4 = (t & 15) * 4;
    float cre[8][4] = {}, cim[8][4] = {};

    for (int kb = 0; kb < kChunk; kb += BBK) {
        int kbase = k0 + kb;
        #pragma unroll
        for (int r = 0; r < 2; r++) {
            int row = arow + r*64;
            float4 vr = *(const float4*)(Are + (size_t)(i0+row)*lda + kbase + ak4);
            float4 vi = *(const float4*)(Aim + (size_t)(i0+row)*lda + kbase + ak4);
            as_re[ak4+0][row] = vr.x; as_re[ak4+1][row] = vr.y;
            as_re[ak4+2][row] = vr.z; as_re[ak4+3][row] = vr.w;
            as_im[ak4+0][row] = vi.x; as_im[ak4+1][row] = vi.y;
            as_im[ak4+2][row] = vi.z; as_im[ak4+3][row] = vi.w;
        }
        {
            float4 vr = *(const float4*)(Bre + (size_t)(kbase+bk)*ldb + j0 + bc4);
            float4 vi = *(const float4*)(Bim + (size_t)(kbase+bk)*ldb + j0 + bc4);
            *(float4*)&bs_re[bk][bc4] = vr;
            *(float4*)&bs_im[bk][bc4] = vi;
        }
        __syncthreads();
        #pragma unroll
        for (int kk = 0; kk < BBK; kk++) {
            float ar[8], ai[8], br[4], bi[4];
            #pragma unroll
            for (int i = 0; i < 8; i++) { ar[i] = as_re[kk][ty*8+i]; ai[i] = as_im[kk][ty*8+i]; }
            #pragma unroll
            for (int j = 0; j < 4; j++) { br[j] = bs_re[kk][tx*4+j]; bi[j] = bs_im[kk][tx*4+j]; }
            #pragma unroll
            for (int i = 0; i < 8; i++)
                #pragma unroll
                for (int j = 0; j < 4; j++) {
                    cre[i][j] += ar[i]*br[j];
                    cre[i][j] -= ai[i]*bi[j];
                    cim[i][j] += ar[i]*bi[j];
                    cim[i][j] += ai[i]*br[j];
                }
        }
        __syncthreads();
    }
    size_t off = (size_t)blockIdx.z * MNpart;
    #pragma unroll
    for (int i = 0; i < 8; i++) {
        int gi = i0 + ty*8 + i, gj = j0 + tx*4;
        *(float4*)(Cre + off + (size_t)gi*ldb + gj) = make_float4(cre[i][0], cre[i][1], cre[i][2], cre[i][3]);
        *(float4*)(Cim + off + (size_t)gi*ldb + gj) = make_float4(cim[i][0], cim[i][1], cim[i][2], cim[i][3]);
    }
}

// ---------------- reduces ----------------
__global__ void reduce_RG(float* __restrict__ Cre, float* __restrict__ Cim, int SK, int ridge) {
    int e = blockIdx.x * 256 + threadIdx.x;
    float sr = 0.f, si = 0.f;
    for (int z = 0; z < SK; z++) { sr += g_part_re[z*65536 + e]; si += g_part_im[z*65536 + e]; }
    if (ridge && (e >> 8) == (e & 255)) sr += 0.01f;
    Cre[e] = sr; Cim[e] = si;
}
__global__ void reduce_sum(float* __restrict__ Cre, float* __restrict__ Cim, int SK) {
    int e = blockIdx.x * 256 + threadIdx.x;
    float sr = 0.f, si = 0.f;
    for (int z = 0; z < SK; z++) { sr += g_part_re[z*65536 + e]; si += g_part_im[z*65536 + e]; }
    Cre[e] = sr; Cim[e] = si;
}
__global__ void reduce_newton(float* __restrict__ Xnre, float* __restrict__ Xnim,
                              const float* __restrict__ Xre, const float* __restrict__ Xim, int SK)
{
    int e = blockIdx.x * 256 + threadIdx.x;
    float sr = 0.f, si = 0.f;
    for (int z = 0; z < SK; z++) { sr += g_part_re[z*65536 + e]; si += g_part_im[z*65536 + e]; }
    Xnre[e] = 2.f*Xre[e] - sr;
    Xnim[e] = 2.f*Xim[e] - si;
}

// ---------------- alpha = tr(R)/||R||_F^2 ; X0 = alpha*I ----------------
__global__ void trace_alpha() {
    __shared__ float red[1024];
    __shared__ float s_fro;
    int t = threadIdx.x;
    float fro = 0.f;
    for (int e = t; e < 65536; e += 1024) {
        float a = g_Rre[e], b = g_Rim[e];
        fro += a*a + b*b;
    }
    red[t] = fro; __syncthreads();
    for (int o = 512; o > 0; o >>= 1) { if (t < o) red[t] += red[t+o]; __syncthreads(); }
    if (t == 0) s_fro = red[0];
    __syncthreads();
    float tr = 0.f;
    for (int i = t; i < 256; i += 1024) tr += g_Rre[i*257];
    red[t] = tr; __syncthreads();
    for (int o = 512; o > 0; o >>= 1) { if (t < o) red[t] += red[t+o]; __syncthreads(); }
    if (t == 0) g_scal[0] = red[0] / s_fro;
}
__global__ void init_X0(float* __restrict__ Xre, float* __restrict__ Xim) {
    int i = blockIdx.x, j = threadIdx.x;
    float a = g_scal[0];
    Xre[i*Mdim + j] = (i == j) ? a : 0.f;
    Xim[i*Mdim + j] = 0.f;
}

// ---------------- Bc = conj(symmetrize(Rinv)) ----------------
__global__ void symm_conj(const float* __restrict__ Xre, const float* __restrict__ Xim,
                          float* __restrict__ Bre, float* __restrict__ Bim) {
    int e = blockIdx.x * 256 + threadIdx.x;
    int i = e >> 8, j = e & 255;
    Bre[e] = 0.5f * (Xre[i*256 + j] + Xre[j*256 + i]);
    Bim[e] = 0.5f * (Xim[j*256 + i] - Xim[i*256 + j]);
}

// ---------------- transpose A -> At [L][M] ----------------
__global__ void transposeA(const float* __restrict__ Are, const float* __restrict__ Aim) {
    __shared__ float t0[32][33], t1[32][33];
    int lb = blockIdx.x * 32, mb = blockIdx.y * 32;
    int x = threadIdx.x, y = threadIdx.y;
    for (int yy = y; yy < 32; yy += 8) {
        t0[yy][x] = Are[(size_t)(mb+yy)*Ldim + lb + x];
        t1[yy][x] = Aim[(size_t)(mb+yy)*Ldim + lb + x];
    }
    __syncthreads();
    for (int yy = y; yy < 32; yy += 8) {
        g_Atre[(size_t)(lb+yy)*Mdim + mb + x] = t0[x][yy];
        g_Atim[(size_t)(lb+yy)*Mdim + mb + x] = t1[x][yy];
    }
}

// ---------------- q, d, v, u (transposed layout) ----------------
__global__ __launch_bounds__(256)
void qduv_kernel(const float* __restrict__ gamma, const float* __restrict__ delta) {
    int wid = threadIdx.x >> 5, lane = threadIdx.x & 31;
    int l = blockIdx.x * 8 + wid;
    const float4* zr  = (const float4*)(g_Ztre + (size_t)l*Mdim);
    const float4* zi  = (const float4*)(g_Ztim + (size_t)l*Mdim);
    const float4* gr  = (const float4*)(g_GZre + (size_t)l*Mdim);
    const float4* gi  = (const float4*)(g_GZim + (size_t)l*Mdim);
    const float4* ar  = (const float4*)(g_Atre + (size_t)l*Mdim);
    const float4* ai  = (const float4*)(g_Atim + (size_t)l*Mdim);
    float q = 0.f, d = 0.f;
    #pragma unroll
    for (int it = 0; it < 2; it++) {
        int k = lane + it*32;
        float4 a = zr[k], b = zi[k], c = gr[k], e = gi[k], f = ar[k], g2 = ai[k];
        q += a.x*c.x + a.y*c.y + a.z*c.z + a.w*c.w
           + b.x*e.x + b.y*e.y + b.z*e.z + b.w*e.w;
        d += a.x*f.x + a.y*f.y + a.z*f.z + a.w*f.w
           - (b.x*g2.x + b.y*g2.y + b.z*g2.z + b.w*g2.w);
    }
    q = warp_sum(q); d = warp_sum(d);
    if (lane == 0) {
        float v = q / (d + 1e-12f);
        float dl = 1.f / (1.f + expf(-delta[0]));
        float p = gamma[l];
        g_v[l] = v;
        g_u[l] = p + dl * (v - p);
    }
}

// ---------------- LayerNorm + kv stats ----------------
__global__ void ln_kernel(const float* __restrict__ ln_w, const float* __restrict__ ln_b,
                          const float* __restrict__ in_w, const float* __restrict__ in_b)
{
    __shared__ float red[512];
    __shared__ float s_mu, s_inv;
    int t = threadIdx.x;
    float s = 0.f;
    for (int i = t; i < Ldim; i += 512) s += g_u[i];
    red[t] = s; __syncthreads();
    for (int o = 256; o > 0; o >>= 1) { if (t < o) red[t] += red[t+o]; __syncthreads(); }
    if (t == 0) s_mu = red[0] / (float)Ldim;
    __syncthreads();
    float mu = s_mu, s2 = 0.f;
    for (int i = t; i < Ldim; i += 512) { float d = g_u[i] - mu; s2 += d*d; }
    red[t] = s2; __syncthreads();
    for (int o = 256; o > 0; o >>= 1) { if (t < o) red[t] += red[t+o]; __syncthreads(); }
    if (t == 0) s_inv = rsqrtf(red[0] / (float)Ldim + 1e-5f);
    __syncthreads();
    float inv = s_inv;
    float w1 = in_w[1], b1 = in_b[1];
    float kmin = 3.4e38f, kmax = -3.4e38f;
    for (int i = t; i < Ldim; i += 512) {
        float up = (g_u[i] - mu) * inv * ln_w[i] + ln_b[i];
        g_up[i] = up;
        float k2 = (up * w1 + b1) * LOG2E_F;
        kmin = fminf(kmin, k2); kmax = fmaxf(kmax, k2);
    }
    red[t] = kmax; __syncthreads();
    for (int o = 256; o > 0; o >>= 1) { if (t < o) red[t] = fmaxf(red[t], red[t+o]); __syncthreads(); }
    if (t == 0) g_scal[2] = red[0];
    __syncthreads();
    red[t] = kmin; __syncthreads();
    for (int o = 256; o > 0; o >>= 1) { if (t < o) red[t] = fminf(red[t], red[t+o]); __syncthreads(); }
    if (t == 0) g_scal[1] = red[0];
}

// ---------------- attention (rank-1 softmax) ----------------
__global__ __launch_bounds__(256)
void attn_kernel(const float* __restrict__ in_w, const float* __restrict__ in_b,
                 const float* __restrict__ out_w, const float* __restrict__ out_b)
{
    __shared__ float skv2[Ldim];
    __shared__ float svv[Ldim];
    int t = threadIdx.x;
    float w0 = in_w[0], b0 = in_b[0];
    float w1 = in_w[1], b1 = in_b[1];
    float w2 = in_w[2], b2 = in_b[2];
    for (int j = t; j < Ldim; j += 256) {
        float up = g_up[j];
        skv2[j] = (up * w1 + b1) * LOG2E_F;
        svv[j]  = up * w2 + b2;
    }
    __syncthreads();
    float k2min = g_scal[1], k2max = g_scal[2];
    float ow = out_w[0], ob = out_b[0];
    int warp = t >> 5, lane = t & 31;
    #pragma unroll
    for (int r = 0; r < 4; r++) {
        int i = blockIdx.x * 32 + warp * 4 + r;
        float qv = g_up[i] * w0 + b0;
        float m2 = (qv >= 0.f) ? qv * k2max : qv * k2min;
        float den = 0.f, num = 0.f;
        for (int j = lane; j < Ldim; j += 32) {
            float arg = qv * skv2[j] - m2;
            float e;
            asm("ex2.approx.f32 %0, %1;" : "=f"(e) : "f"(arg));
            den += e;
            num = fmaf(e, svv[j], num);
        }
        den = warp_sum(den); num = warp_sum(num);
        if (lane == 0) g_attn[i] = (num / den) * ow + ob;
    }
}

// ---------------- gate matvec + final fuse ----------------
__global__ __launch_bounds__(256)
void final_kernel(const float* __restrict__ W, const float* __restrict__ gb,
                  const float* __restrict__ gamma, const float* __restrict__ lmbda,
                  float* __restrict__ out)
{
    int warp = threadIdx.x >> 5, lane = threadIdx.x & 31;
    int i = blockIdx.x * 8 + warp;
    const float4* Wr = (const float4*)(W + (size_t)i * Ldim);
    const float4* U4 = (const float4*)g_u;
    float acc = 0.f;
    for (int k = lane; k < Ldim/4; k += 32) {
        float4 w4 = Wr[k]; float4 u4 = U4[k];
        acc += w4.x*u4.x + w4.y*u4.y + w4.z*u4.z + w4.w*u4.w;
    }
    acc = warp_sum(acc);
    if (lane == 0) {
        float z = acc + gb[i];
        float g = 1.f / (1.f + expf(-z));
        float s = g * g_v[i] + (1.f - g) * gamma[i] + g_attn[i] - lmbda[0];
        out[i] = fmaxf(s, 0.f);
    }
}

// ---------------- launch ----------------
extern "C" void kernel_launch(void* const* d_in, const int* in_sizes, int n_in,
                              void* d_out, int out_size)
{
    const float* gamma  = (const float*)d_in[0];
    const float* A_re   = (const float*)d_in[1];
    const float* A_im   = (const float*)d_in[2];
    const float* X_re   = (const float*)d_in[3];
    const float* X_im   = (const float*)d_in[4];
    const float* ln_w   = (const float*)d_in[5];
    const float* ln_b   = (const float*)d_in[6];
    const float* in_w   = (const float*)d_in[7];
    const float* in_b   = (const float*)d_in[8];
    const float* out_w  = (const float*)d_in[9];
    const float* out_b  = (const float*)d_in[10];
    const float* gate_W = (const float*)d_in[11];
    const float* gate_b = (const float*)d_in[12];
    const float* delta  = (const float*)d_in[13];
    const float* lmbda  = (const float*)d_in[14];
    float* out = (float*)d_out;

    cudaFuncSetAttribute(cgemm_mma, cudaFuncAttributeMaxDynamicSharedMemorySize, ENG_SMEM2);

    float *Rre,*Rim,*Gre,*Gim,*Xare,*Xaim,*Xbre,*Xbim,*Pre,*Pim;
    float *pre,*pim,*Atre,*Atim,*Ztre,*Ztim,*GZre,*GZim;
    cudaGetSymbolAddress((void**)&Rre,  g_Rre);   cudaGetSymbolAddress((void**)&Rim,  g_Rim);
    cudaGetSymbolAddress((void**)&Gre,  g_Gre);   cudaGetSymbolAddress((void**)&Gim,  g_Gim);
    cudaGetSymbolAddress((void**)&Xare, g_Xa_re); cudaGetSymbolAddress((void**)&Xaim, g_Xa_im);
    cudaGetSymbolAddress((void**)&Xbre, g_Xb_re); cudaGetSymbolAddress((void**)&Xbim, g_Xb_im);
    cudaGetSymbolAddress((void**)&Pre,  g_P_re);  cudaGetSymbolAddress((void**)&Pim,  g_P_im);
    cudaGetSymbolAddress((void**)&pre,  g_part_re); cudaGetSymbolAddress((void**)&pim, g_part_im);
    cudaGetSymbolAddress((void**)&Atre, g_Atre);  cudaGetSymbolAddress((void**)&Atim, g_Atim);
    cudaGetSymbolAddress((void**)&Ztre, g_Ztre);  cudaGetSymbolAddress((void**)&Ztim, g_Ztim);
    cudaGetSymbolAddress((void**)&GZre, g_GZre);  cudaGetSymbolAddress((void**)&GZim, g_GZim);

    // At = A^T (planar)
    transposeA<<<dim3(128, 8), dim3(32, 8)>>>(A_re, A_im);

    // R = (A*diag(gamma)) A^H + ridge I : fp32 high-ILP csyrk, 16-way k-split
    csyrk_big<<<dim3(4,2,16), 256>>>(pre, pim, A_re, A_im, gamma, Ldim, 256);
    reduce_RG<<<256, 256>>>(Rre, Rim, 16, 1);

    // G = X X^H : 2-split conj MMA (q-chain), 16-way k-split
    cgemm_mma<<<dim3(2,2,32), 256, ENG_SMEM2>>>(X_re, X_im, Tdim, X_re, X_im, Tdim,
                                                pre, pim, Mdim, 128, 1, nullptr, 65536);
    reduce_RG<<<256, 256>>>(Gre, Gim, 16, 0);

    // alpha and X0 = alpha*I
    trace_alpha<<<1, 1024>>>();
    init_X0<<<256, 256>>>(Xare, Xaim);

    // order-2 Newton (fp32 high-ILP): Xn = 2X - X(RX), 7 iterations
    float *Xc_re = Xare, *Xc_im = Xaim, *Xn_re = Xbre, *Xn_im = Xbim;
    for (int it = 0; it < 7; ++it) {
        cgemm_big<<<dim3(4,2,16), 256>>>(pre, pim, Rre, Rim, Mdim,
                                         Xc_re, Xc_im, Mdim, 16, 65536);
        reduce_sum<<<256, 256>>>(Pre, Pim, 16);
        cgemm_big<<<dim3(4,2,16), 256>>>(pre, pim, Xc_re, Xc_im, Mdim,
                                         Pre, Pim, Mdim, 16, 65536);
        reduce_newton<<<256, 256>>>(Xn_re, Xn_im, Xc_re, Xc_im, 16);
        float* tmp;
        tmp = Xc_re; Xc_re = Xn_re; Xn_re = tmp;
        tmp = Xc_im; Xc_im = Xn_im; Xn_im = tmp;
    }

    // Bc = conj(symmetrized Rinv)
    symm_conj<<<256, 256>>>(Xc_re, Xc_im, Pre, Pim);

    // Zt[l,m] = sum_k At[l,k] * Bc[k,m]   (fp32 high-ILP, full-K, no split)
    cgemm_big<<<dim3(4,32,1), 256>>>(Ztre, Ztim, Atre, Atim, Mdim,
                                     Pre, Pim, Mdim, 256, 0);

    // GZt[l,m] = sum_k Zt[l,k] * G[m,k]   (2-split MMA, q-chain)
    cgemm_mma<<<dim3(2,32,2), 256, ENG_SMEM2>>>(Ztre, Ztim, Mdim, Gre, Gim, Mdim,
                                                GZre, GZim, Mdim, 256, 0, nullptr, 0);

    qduv_kernel<<<512, 256>>>(gamma, delta);
    ln_kernel<<<1, 512>>>(ln_w, ln_b, in_w, in_b);
    attn_kernel<<<128, 256>>>(in_w, in_b, out_w, out_b);
    final_kernel<<<512, 256>>>(gate_W, gate_b, gamma, lmbda, out);
}

// round 14
// speedup vs baseline: 1.5000x; 1.0490x over previous
#include <cuda_runtime.h>
#include <cuda_bf16.h>
#include <math.h>
#include <stdint.h>

#define Mdim 256
#define Ldim 4096
#define Tdim 2048
#define LOG2E_F 1.4426950408889634f

// ---------------- device scratch ----------------
__device__ float g_Rre[Mdim*Mdim], g_Rim[Mdim*Mdim];
__device__ float g_Gre[Mdim*Mdim], g_Gim[Mdim*Mdim];
__device__ float g_Xa_re[Mdim*Mdim], g_Xa_im[Mdim*Mdim];
__device__ float g_Xb_re[Mdim*Mdim], g_Xb_im[Mdim*Mdim];
__device__ float g_P_re[Mdim*Mdim],  g_P_im[Mdim*Mdim];
__device__ float g_part_re[32*Mdim*Mdim], g_part_im[32*Mdim*Mdim];
__device__ float g_Atre[Ldim*Mdim], g_Atim[Ldim*Mdim];
__device__ float g_Ztre[Ldim*Mdim], g_Ztim[Ldim*Mdim];
__device__ float g_GZre[Ldim*Mdim], g_GZim[Ldim*Mdim];
__device__ float g_v[Ldim], g_u[Ldim], g_up[Ldim], g_attn[Ldim];
__device__ float g_scal[4];   // [0]=alpha  [1]=kv2min [2]=kv2max

__device__ __forceinline__ float warp_sum(float v) {
    #pragma unroll
    for (int o = 16; o > 0; o >>= 1) v += __shfl_xor_sync(0xffffffffu, v, o);
    return v;
}

// ---------------- smem helpers ----------------
__device__ __forceinline__ uint32_t smem_u32(const void* p) {
    uint32_t a;
    asm("{ .reg .u64 t; cvta.to.shared.u64 t, %1; cvt.u32.u64 %0, t; }" : "=r"(a) : "l"(p));
    return a;
}
__device__ __forceinline__ uint32_t lds32(uint32_t a) {
    uint32_t v;
    asm volatile("ld.shared.b32 %0, [%1];" : "=r"(v) : "r"(a));
    return v;
}
__device__ __forceinline__ void sts128(uint32_t a, uint32_t x, uint32_t y,
                                       uint32_t z, uint32_t w) {
    asm volatile("st.shared.v4.b32 [%0], {%1,%2,%3,%4};"
                 :: "r"(a), "r"(x), "r"(y), "r"(z), "r"(w) : "memory");
}
__device__ __forceinline__ uint32_t cvt_tf32(float x) {
    uint32_t r;
    asm("cvt.rna.tf32.f32 %0, %1;" : "=r"(r) : "f"(x));
    return r;
}
#define MMAT32(d, a, b) \
    asm volatile("mma.sync.aligned.m16n8k8.row.col.f32.tf32.tf32.f32 " \
        "{%0,%1,%2,%3},{%4,%5,%6,%7},{%8,%9},{%0,%1,%2,%3};" \
        : "+f"((d)[0]), "+f"((d)[1]), "+f"((d)[2]), "+f"((d)[3]) \
        : "r"((a)[0]), "r"((a)[1]), "r"((a)[2]), "r"((a)[3]), "r"((b)[0]), "r"((b)[1]))

#define PITCHB 144
#define PLSZ   18432
#define ENG_SMEM2 (8*PLSZ)

// convert one 128x32 fp32 tile -> 2 tf32 split planes in smem (sign/weight folded)
__device__ __forceinline__ void conv_tile2(uint32_t sa, int tbase,
                                           const float* __restrict__ src, int row0, int ld,
                                           int k0, const float* __restrict__ w, float sgn)
{
    int tid = threadIdx.x;
    uint32_t p0 = sa + tbase*PLSZ;
    uint32_t p1 = p0 + PLSZ;
    #pragma unroll
    for (int p = 0; p < 4; p++) {
        int idx = tid + p*256;
        int row = idx >> 3, c4 = idx & 7;
        float4 v = *(const float4*)(src + (size_t)(row0+row)*ld + k0 + c4*4);
        if (w) {
            float4 wv = *(const float4*)(w + k0 + c4*4);
            v.x *= wv.x; v.y *= wv.y; v.z *= wv.z; v.w *= wv.w;
        }
        v.x *= sgn; v.y *= sgn; v.z *= sgn; v.w *= sgn;
        uint32_t h0 = cvt_tf32(v.x), h1 = cvt_tf32(v.y);
        uint32_t h2 = cvt_tf32(v.z), h3 = cvt_tf32(v.w);
        uint32_t m0 = cvt_tf32(v.x - __uint_as_float(h0));
        uint32_t m1 = cvt_tf32(v.y - __uint_as_float(h1));
        uint32_t m2 = cvt_tf32(v.z - __uint_as_float(h2));
        uint32_t m3 = cvt_tf32(v.w - __uint_as_float(h3));
        uint32_t off = row*PITCHB + c4*16;
        sts128(p0 + off, h0, h1, h2, h3);
        sts128(p1 + off, m0, m1, m2, m3);
    }
}

// ============================================================================
// split-tf32 complex GEMM via mma.sync m16n8k8 (q-chain ONLY — G and GZt)
// ============================================================================
__global__ __launch_bounds__(256, 1)
void cgemm_mma(const float* __restrict__ Pre, const float* __restrict__ Pim, int ldp,
               const float* __restrict__ Qre, const float* __restrict__ Qim, int ldq,
               float* __restrict__ Cre, float* __restrict__ Cim, int ldc,
               int Kper, int conj, const float* __restrict__ w, int partElems)
{
    extern __shared__ char dsm[];
    uint32_t sa = smem_u32(dsm);
    int tid = threadIdx.x;
    int wid = tid >> 5, lane = tid & 31;
    int g = lane >> 2, t4 = lane & 3;
    int warpM = wid >> 2, warpN = wid & 3;
    int i0 = blockIdx.y * 128, j0 = blockIdx.x * 128;
    int plane = blockIdx.z & 1, ks = blockIdx.z >> 1;

    const float* A0 = (conj && plane) ? Pim : Pre;
    const float* A1 = (conj && plane) ? Pre : Pim;
    float s1 = ((conj && plane) || (!conj && !plane)) ? -1.f : 1.f;
    const float* B0 = (!conj && plane) ? Qim : Qre;
    const float* B1 = (!conj && plane) ? Qre : Qim;

    float acc[4][4][4] = {};

    int nCh = Kper >> 5;
    for (int ch = 0; ch < nCh; ch++) {
        int k0 = ks * Kper + ch * 32;
        conv_tile2(sa, 0, A0, i0, ldp, k0, w, 1.f);
        conv_tile2(sa, 2, A1, i0, ldp, k0, w, s1);
        conv_tile2(sa, 4, B0, j0, ldq, k0, (const float*)0, 1.f);
        conv_tile2(sa, 6, B1, j0, ldq, k0, (const float*)0, 1.f);
        __syncthreads();

        const int ta[6] = {0, 0, 1, 2, 2, 3};
        const int tb[6] = {4, 5, 4, 6, 7, 6};
        #pragma unroll
        for (int ps = 0; ps < 6; ps++) {
            uint32_t ab = sa + ta[ps]*PLSZ;
            uint32_t bb = sa + tb[ps]*PLSZ;
            #pragma unroll
            for (int kk = 0; kk < 4; kk++) {
                uint32_t afr[4][4], bfr[4][2];
                #pragma unroll
                for (int am = 0; am < 4; am++) {
                    uint32_t r0 = ab + (warpM*64 + am*16 + g)*PITCHB + (kk*8 + t4)*4;
                    afr[am][0] = lds32(r0);
                    afr[am][1] = lds32(r0 + 8*PITCHB);
                    afr[am][2] = lds32(r0 + 16);
                    afr[am][3] = lds32(r0 + 8*PITCHB + 16);
                }
                #pragma unroll
                for (int bn = 0; bn < 4; bn++) {
                    uint32_t r0 = bb + (warpN*32 + bn*8 + g)*PITCHB + (kk*8 + t4)*4;
                    bfr[bn][0] = lds32(r0);
                    bfr[bn][1] = lds32(r0 + 16);
                }
                #pragma unroll
                for (int am = 0; am < 4; am++)
                    #pragma unroll
                    for (int bn = 0; bn < 4; bn++)
                        MMAT32(acc[am][bn], afr[am], bfr[bn]);
            }
        }
        __syncthreads();
    }

    float* dst = plane ? Cim : Cre;
    size_t zoff = (size_t)ks * partElems;
    #pragma unroll
    for (int am = 0; am < 4; am++) {
        #pragma unroll
        for (int bn = 0; bn < 4; bn++) {
            int r = i0 + warpM*64 + am*16 + g;
            int c = j0 + warpN*32 + bn*8 + 2*t4;
            float2 v0 = make_float2(acc[am][bn][0], acc[am][bn][1]);
            float2 v1 = make_float2(acc[am][bn][2], acc[am][bn][3]);
            *(float2*)(dst + zoff + (size_t)r*ldc + c) = v0;
            *(float2*)(dst + zoff + (size_t)(r+8)*ldc + c) = v1;
        }
    }
}

// ============================================================================
// High-ILP fp32 SIMT complex GEMMs: BM=128, BN=64, BK=16, TM=8, TN=4.
// ============================================================================
#define BBM 128
#define BBN 64
#define BBK 16

// Hermitian csyrk: computes 6 lower/diagonal tiles of C = (A*diag(w)) A^H.
// blockIdx.x indexes the tile table; upper-right 128x128 filled by mirror_R.
__global__ __launch_bounds__(256)
void csyrk_big(float* __restrict__ Pre, float* __restrict__ Pim,
               const float* __restrict__ Are, const float* __restrict__ Aim,
               const float* __restrict__ w, int lda, int kChunk)
{
    __shared__ float as_re[BBK][BBM+4], as_im[BBK][BBM+4];
    __shared__ float bs_re[BBK][BBN+4], bs_im[BBK][BBN+4];
    const int tbi[6] = {0, 0, 128, 128, 128, 128};
    const int tbj[6] = {0, 64, 0, 64, 128, 192};
    int i0 = tbi[blockIdx.x], j0 = tbj[blockIdx.x];
    int k0 = blockIdx.z * kChunk;
    int t  = threadIdx.x;
    int tx = t & 15, ty = t >> 4;
    int arow = t >> 2, ak4 = (t & 3) * 4;
    float cre[8][4] = {}, cim[8][4] = {};

    for (int kb = 0; kb < kChunk; kb += BBK) {
        int kbase = k0 + kb;
        float4 wv;
        if (w) wv = *(const float4*)(w + kbase + ak4);
        else   wv = make_float4(1.f, 1.f, 1.f, 1.f);
        #pragma unroll
        for (int r = 0; r < 2; r++) {
            int row = arow + r*64;
            float4 vr = *(const float4*)(Are + (size_t)(i0+row)*lda + kbase + ak4);
            float4 vi = *(const float4*)(Aim + (size_t)(i0+row)*lda + kbase + ak4);
            as_re[ak4+0][row] = vr.x*wv.x; as_re[ak4+1][row] = vr.y*wv.y;
            as_re[ak4+2][row] = vr.z*wv.z; as_re[ak4+3][row] = vr.w*wv.w;
            as_im[ak4+0][row] = vi.x*wv.x; as_im[ak4+1][row] = vi.y*wv.y;
            as_im[ak4+2][row] = vi.z*wv.z; as_im[ak4+3][row] = vi.w*wv.w;
        }
        {
            int col = t >> 2;
            float4 vr = *(const float4*)(Are + (size_t)(j0+col)*lda + kbase + ak4);
            float4 vi = *(const float4*)(Aim + (size_t)(j0+col)*lda + kbase + ak4);
            bs_re[ak4+0][col] = vr.x; bs_re[ak4+1][col] = vr.y;
            bs_re[ak4+2][col] = vr.z; bs_re[ak4+3][col] = vr.w;
            bs_im[ak4+0][col] = vi.x; bs_im[ak4+1][col] = vi.y;
            bs_im[ak4+2][col] = vi.z; bs_im[ak4+3][col] = vi.w;
        }
        __syncthreads();
        #pragma unroll
        for (int kk = 0; kk < BBK; kk++) {
            float ar[8], ai[8], br[4], bi[4];
            #pragma unroll
            for (int i = 0; i < 8; i++) { ar[i] = as_re[kk][ty*8+i]; ai[i] = as_im[kk][ty*8+i]; }
            #pragma unroll
            for (int j = 0; j < 4; j++) { br[j] = bs_re[kk][tx*4+j]; bi[j] = bs_im[kk][tx*4+j]; }
            #pragma unroll
            for (int i = 0; i < 8; i++)
                #pragma unroll
                for (int j = 0; j < 4; j++) {
                    cre[i][j] += ar[i]*br[j];
                    cre[i][j] += ai[i]*bi[j];
                    cim[i][j] += ai[i]*br[j];
                    cim[i][j] -= ar[i]*bi[j];
                }
        }
        __syncthreads();
    }
    size_t off = (size_t)blockIdx.z * (Mdim*Mdim);
    #pragma unroll
    for (int i = 0; i < 8; i++) {
        int gi = i0 + ty*8 + i, gj = j0 + tx*4;
        *(float4*)(Pre + off + (size_t)gi*Mdim + gj) = make_float4(cre[i][0], cre[i][1], cre[i][2], cre[i][3]);
        *(float4*)(Pim + off + (size_t)gi*Mdim + gj) = make_float4(cim[i][0], cim[i][1], cim[i][2], cim[i][3]);
    }
}

// nn variant: C[i,j] = sum_k A[i,k]*B[k,j]
__global__ __launch_bounds__(256)
void cgemm_big(float* __restrict__ Cre, float* __restrict__ Cim,
               const float* __restrict__ Are, const float* __restrict__ Aim, int lda,
               const float* __restrict__ Bre, const float* __restrict__ Bim, int ldb,
               int kChunk, int MNpart)
{
    __shared__ float as_re[BBK][BBM+4], as_im[BBK][BBM+4];
    __shared__ float bs_re[BBK][BBN+4], bs_im[BBK][BBN+4];
    int i0 = blockIdx.y * BBM, j0 = blockIdx.x * BBN;
    int k0 = blockIdx.z * kChunk;
    int t  = threadIdx.x;
    int tx = t & 15, ty = t >> 4;
    int arow = t >> 2, ak4 = (t & 3) * 4;
    int bk = t >> 4, bc4 = (t & 15) * 4;
    float cre[8][4] = {}, cim[8][4] = {};

    for (int kb = 0; kb < kChunk; kb += BBK) {
        int kbase = k0 + kb;
        #pragma unroll
        for (int r = 0; r < 2; r++) {
            int row = arow + r*64;
            float4 vr = *(const float4*)(Are + (size_t)(i0+row)*lda + kbase + ak4);
            float4 vi = *(const float4*)(Aim + (size_t)(i0+row)*lda + kbase + ak4);
            as_re[ak4+0][row] = vr.x; as_re[ak4+1][row] = vr.y;
            as_re[ak4+2][row] = vr.z; as_re[ak4+3][row] = vr.w;
            as_im[ak4+0][row] = vi.x; as_im[ak4+1][row] = vi.y;
            as_im[ak4+2][row] = vi.z; as_im[ak4+3][row] = vi.w;
        }
        {
            float4 vr = *(const float4*)(Bre + (size_t)(kbase+bk)*ldb + j0 + bc4);
            float4 vi = *(const float4*)(Bim + (size_t)(kbase+bk)*ldb + j0 + bc4);
            *(float4*)&bs_re[bk][bc4] = vr;
            *(float4*)&bs_im[bk][bc4] = vi;
        }
        __syncthreads();
        #pragma unroll
        for (int kk = 0; kk < BBK; kk++) {
            float ar[8], ai[8], br[4], bi[4];
            #pragma unroll
            for (int i = 0; i < 8; i++) { ar[i] = as_re[kk][ty*8+i]; ai[i] = as_im[kk][ty*8+i]; }
            #pragma unroll
            for (int j = 0; j < 4; j++) { br[j] = bs_re[kk][tx*4+j]; bi[j] = bs_im[kk][tx*4+j]; }
            #pragma unroll
            for (int i = 0; i < 8; i++)
                #pragma unroll
                for (int j = 0; j < 4; j++) {
                    cre[i][j] += ar[i]*br[j];
                    cre[i][j] -= ai[i]*bi[j];
                    cim[i][j] += ar[i]*bi[j];
                    cim[i][j] += ai[i]*br[j];
                }
        }
        __syncthreads();
    }
    size_t off = (size_t)blockIdx.z * MNpart;
    #pragma unroll
    for (int i = 0; i < 8; i++) {
        int gi = i0 + ty*8 + i, gj = j0 + tx*4;
        *(float4*)(Cre + off + (size_t)gi*ldb + gj) = make_float4(cre[i][0], cre[i][1], cre[i][2], cre[i][3]);
        *(float4*)(Cim + off + (size_t)gi*ldb + gj) = make_float4(cim[i][0], cim[i][1], cim[i][2], cim[i][3]);
    }
}

// nn variant with fused B-reduction: B[k][j] = sum_z Bpart[z][k][j] (ascending z,
// same order as reduce_sum — deterministic identical values).
__global__ __launch_bounds__(256)
void cgemm_fsum(float* __restrict__ Cre, float* __restrict__ Cim,
                const float* __restrict__ Are, const float* __restrict__ Aim, int lda,
                const float* __restrict__ Bpre, const float* __restrict__ Bpim, int ldb,
                int SK, int kChunk, int MNpart)
{
    __shared__ float as_re[BBK][BBM+4], as_im[BBK][BBM+4];
    __shared__ float bs_re[BBK][BBN+4], bs_im[BBK][BBN+4];
    int i0 = blockIdx.y * BBM, j0 = blockIdx.x * BBN;
    int k0 = blockIdx.z * kChunk;
    int t  = threadIdx.x;
    int tx = t & 15, ty = t >> 4;
    int arow = t >> 2, ak4 = (t & 3) * 4;
    int bk = t >> 4, bc4 = (t & 15) * 4;
    float cre[8][4] = {}, cim[8][4] = {};

    for (int kb = 0; kb < kChunk; kb += BBK) {
        int kbase = k0 + kb;
        #pragma unroll
        for (int r = 0; r < 2; r++) {
            int row = arow + r*64;
            float4 vr = *(const float4*)(Are + (size_t)(i0+row)*lda + kbase + ak4);
            float4 vi = *(const float4*)(Aim + (size_t)(i0+row)*lda + kbase + ak4);
            as_re[ak4+0][row] = vr.x; as_re[ak4+1][row] = vr.y;
            as_re[ak4+2][row] = vr.z; as_re[ak4+3][row] = vr.w;
            as_im[ak4+0][row] = vi.x; as_im[ak4+1][row] = vi.y;
            as_im[ak4+2][row] = vi.z; as_im[ak4+3][row] = vi.w;
        }
        {
            size_t eoff = (size_t)(kbase+bk)*ldb + j0 + bc4;
            float4 vr = make_float4(0.f,0.f,0.f,0.f), vi = make_float4(0.f,0.f,0.f,0.f);
            for (int z = 0; z < SK; z++) {
                float4 pr = *(const float4*)(Bpre + (size_t)z*65536 + eoff);
                float4 pi = *(const float4*)(Bpim + (size_t)z*65536 + eoff);
                vr.x += pr.x; vr.y += pr.y; vr.z += pr.z; vr.w += pr.w;
                vi.x += pi.x; vi.y += pi.y; vi.z += pi.z; vi.w += pi.w;
            }
            *(float4*)&bs_re[bk][bc4] = vr;
            *(float4*)&bs_im[bk][bc4] = vi;
        }
        __syncthreads();
        #pragma unroll
        for (int kk = 0; kk < BBK; kk++) {
            float ar[8], ai[8], br[4], bi[4];
            #pragma unroll
            for (int i = 0; i < 8; i++) { ar[i] = as_re[kk][ty*8+i]; ai[i] = as_im[kk][ty*8+i]; }
            #pragma unroll
            for (int j = 0; j < 4; j++) { br[j] = bs_re[kk][tx*4+j]; bi[j] = bs_im[kk][tx*4+j]; }
            #pragma unroll
            for (int i = 0; i < 8; i++)
                #pragma unroll
                for (int j = 0; j < 4; j++) {
                    cre[i][j] += ar[i]*br[j];
                    cre[i][j] -= ai[i]*bi[j];
                    cim[i][j] += ar[i]*bi[j];
                    cim[i][j] += ai[i]*br[j];
                }
        }
        __syncthreads();
    }
    size_t off = (size_t)blockIdx.z * MNpart;
    #pragma unroll
    for (int i = 0; i < 8; i++) {
        int gi = i0 + ty*8 + i, gj = j0 + tx*4;
        *(float4*)(Cre + off + (size_t)gi*ldb + gj) = make_float4(cre[i][0], cre[i][1], cre[i][2], cre[i][3]);
        *(float4*)(Cim + off + (size_t)gi*ldb + gj) = make_float4(cim[i][0], cim[i][1], cim[i][2], cim[i][3]);
    }
}

// ---------------- reduces ----------------
__global__ void reduce_RG(float* __restrict__ Cre, float* __restrict__ Cim, int SK, int ridge) {
    int e = blockIdx.x * 256 + threadIdx.x;
    float sr = 0.f, si = 0.f;
    for (int z = 0; z < SK; z++) { sr += g_part_re[z*65536 + e]; si += g_part_im[z*65536 + e]; }
    if (ridge && (e >> 8) == (e & 255)) sr += 0.01f;
    Cre[e] = sr; Cim[e] = si;
}
// mirror upper-right 128x128 block of Hermitian R: R[i][j] = conj(R[j][i])
__global__ void mirror_R() {
    int e = blockIdx.x * 256 + threadIdx.x;      // 16384 elements
    int i = e >> 7, j = 128 + (e & 127);
    g_Rre[i*256 + j] =  g_Rre[j*256 + i];
    g_Rim[i*256 + j] = -g_Rim[j*256 + i];
}
// Xn = 2*X - sum_z part[z + zoff]
__global__ void reduce_newton(float* __restrict__ Xnre, float* __restrict__ Xnim,
                              const float* __restrict__ Xre, const float* __restrict__ Xim,
                              int SK, int zoff)
{
    int e = blockIdx.x * 256 + threadIdx.x;
    float sr = 0.f, si = 0.f;
    for (int z = zoff; z < zoff + SK; z++) { sr += g_part_re[z*65536 + e]; si += g_part_im[z*65536 + e]; }
    Xnre[e] = 2.f*Xre[e] - sr;
    Xnim[e] = 2.f*Xim[e] - si;
}

// ---------------- alpha = tr(R)/||R||_F^2 ; X1 = 2aI - a^2 R (free Newton step) ----------------
__global__ void trace_alpha() {
    __shared__ float red[1024];
    __shared__ float s_fro;
    int t = threadIdx.x;
    float fro = 0.f;
    for (int e = t; e < 65536; e += 1024) {
        float a = g_Rre[e], b = g_Rim[e];
        fro += a*a + b*b;
    }
    red[t] = fro; __syncthreads();
    for (int o = 512; o > 0; o >>= 1) { if (t < o) red[t] += red[t+o]; __syncthreads(); }
    if (t == 0) s_fro = red[0];
    __syncthreads();
    float tr = 0.f;
    for (int i = t; i < 256; i += 1024) tr += g_Rre[i*257];
    red[t] = tr; __syncthreads();
    for (int o = 512; o > 0; o >>= 1) { if (t < o) red[t] += red[t+o]; __syncthreads(); }
    if (t == 0) g_scal[0] = red[0] / s_fro;
}
__global__ void init_X1(float* __restrict__ Xre, float* __restrict__ Xim) {
    int e = blockIdx.x * 256 + threadIdx.x;
    int i = e >> 8, j = e & 255;
    float a = g_scal[0];
    float a2 = a * a;
    Xre[e] = -a2 * g_Rre[e] + ((i == j) ? 2.f*a : 0.f);
    Xim[e] = -a2 * g_Rim[e];
}

// ---------------- Bc = conj(symmetrize(Rinv)) ----------------
__global__ void symm_conj(const float* __restrict__ Xre, const float* __restrict__ Xim,
                          float* __restrict__ Bre, float* __restrict__ Bim) {
    int e = blockIdx.x * 256 + threadIdx.x;
    int i = e >> 8, j = e & 255;
    Bre[e] = 0.5f * (Xre[i*256 + j] + Xre[j*256 + i]);
    Bim[e] = 0.5f * (Xim[j*256 + i] - Xim[i*256 + j]);
}

// ---------------- transpose A -> At [L][M] ----------------
__global__ void transposeA(const float* __restrict__ Are, const float* __restrict__ Aim) {
    __shared__ float t0[32][33], t1[32][33];
    int lb = blockIdx.x * 32, mb = blockIdx.y * 32;
    int x = threadIdx.x, y = threadIdx.y;
    for (int yy = y; yy < 32; yy += 8) {
        t0[yy][x] = Are[(size_t)(mb+yy)*Ldim + lb + x];
        t1[yy][x] = Aim[(size_t)(mb+yy)*Ldim + lb + x];
    }
    __syncthreads();
    for (int yy = y; yy < 32; yy += 8) {
        g_Atre[(size_t)(lb+yy)*Mdim + mb + x] = t0[x][yy];
        g_Atim[(size_t)(lb+yy)*Mdim + mb + x] = t1[x][yy];
    }
}

// ---------------- q, d, v, u (transposed layout) ----------------
__global__ __launch_bounds__(256)
void qduv_kernel(const float* __restrict__ gamma, const float* __restrict__ delta) {
    int wid = threadIdx.x >> 5, lane = threadIdx.x & 31;
    int l = blockIdx.x * 8 + wid;
    const float4* zr  = (const float4*)(g_Ztre + (size_t)l*Mdim);
    const float4* zi  = (const float4*)(g_Ztim + (size_t)l*Mdim);
    const float4* gr  = (const float4*)(g_GZre + (size_t)l*Mdim);
    const float4* gi  = (const float4*)(g_GZim + (size_t)l*Mdim);
    const float4* ar  = (const float4*)(g_Atre + (size_t)l*Mdim);
    const float4* ai  = (const float4*)(g_Atim + (size_t)l*Mdim);
    float q = 0.f, d = 0.f;
    #pragma unroll
    for (int it = 0; it < 2; it++) {
        int k = lane + it*32;
        float4 a = zr[k], b = zi[k], c = gr[k], e = gi[k], f = ar[k], g2 = ai[k];
        q += a.x*c.x + a.y*c.y + a.z*c.z + a.w*c.w
           + b.x*e.x + b.y*e.y + b.z*e.z + b.w*e.w;
        d += a.x*f.x + a.y*f.y + a.z*f.z + a.w*f.w
           - (b.x*g2.x + b.y*g2.y + b.z*g2.z + b.w*g2.w);
    }
    q = warp_sum(q); d = warp_sum(d);
    if (lane == 0) {
        float v = q / (d + 1e-12f);
        float dl = 1.f / (1.f + expf(-delta[0]));
        float p = gamma[l];
        g_v[l] = v;
        g_u[l] = p + dl * (v - p);
    }
}

// ---------------- LayerNorm + kv stats ----------------
__global__ void ln_kernel(const float* __restrict__ ln_w, const float* __restrict__ ln_b,
                          const float* __restrict__ in_w, const float* __restrict__ in_b)
{
    __shared__ float red[512];
    __shared__ float s_mu, s_inv;
    int t = threadIdx.x;
    float s = 0.f;
    for (int i = t; i < Ldim; i += 512) s += g_u[i];
    red[t] = s; __syncthreads();
    for (int o = 256; o > 0; o >>= 1) { if (t < o) red[t] += red[t+o]; __syncthreads(); }
    if (t == 0) s_mu = red[0] / (float)Ldim;
    __syncthreads();
    float mu = s_mu, s2 = 0.f;
    for (int i = t; i < Ldim; i += 512) { float d = g_u[i] - mu; s2 += d*d; }
    red[t] = s2; __syncthreads();
    for (int o = 256; o > 0; o >>= 1) { if (t < o) red[t] += red[t+o]; __syncthreads(); }
    if (t == 0) s_inv = rsqrtf(red[0] / (float)Ldim + 1e-5f);
    __syncthreads();
    float inv = s_inv;
    float w1 = in_w[1], b1 = in_b[1];
    float kmin = 3.4e38f, kmax = -3.4e38f;
    for (int i = t; i < Ldim; i += 512) {
        float up = (g_u[i] - mu) * inv * ln_w[i] + ln_b[i];
        g_up[i] = up;
        float k2 = (up * w1 + b1) * LOG2E_F;
        kmin = fminf(kmin, k2); kmax = fmaxf(kmax, k2);
    }
    red[t] = kmax; __syncthreads();
    for (int o = 256; o > 0; o >>= 1) { if (t < o) red[t] = fmaxf(red[t], red[t+o]); __syncthreads(); }
    if (t == 0) g_scal[2] = red[0];
    __syncthreads();
    red[t] = kmin; __syncthreads();
    for (int o = 256; o > 0; o >>= 1) { if (t < o) red[t] = fminf(red[t], red[t+o]); __syncthreads(); }
    if (t == 0) g_scal[1] = red[0];
}

// ---------------- attention (rank-1 softmax) ----------------
__global__ __launch_bounds__(256)
void attn_kernel(const float* __restrict__ in_w, const float* __restrict__ in_b,
                 const float* __restrict__ out_w, const float* __restrict__ out_b)
{
    __shared__ float skv2[Ldim];
    __shared__ float svv[Ldim];
    int t = threadIdx.x;
    float w0 = in_w[0], b0 = in_b[0];
    float w1 = in_w[1], b1 = in_b[1];
    float w2 = in_w[2], b2 = in_b[2];
    for (int j = t; j < Ldim; j += 256) {
        float up = g_up[j];
        skv2[j] = (up * w1 + b1) * LOG2E_F;
        svv[j]  = up * w2 + b2;
    }
    __syncthreads();
    float k2min = g_scal[1], k2max = g_scal[2];
    float ow = out_w[0], ob = out_b[0];
    int warp = t >> 5, lane = t & 31;
    #pragma unroll
    for (int r = 0; r < 4; r++) {
        int i = blockIdx.x * 32 + warp * 4 + r;
        float qv = g_up[i] * w0 + b0;
        float m2 = (qv >= 0.f) ? qv * k2max : qv * k2min;
        float den = 0.f, num = 0.f;
        for (int j = lane; j < Ldim; j += 32) {
            float arg = qv * skv2[j] - m2;
            float e;
            asm("ex2.approx.f32 %0, %1;" : "=f"(e) : "f"(arg));
            den += e;
            num = fmaf(e, svv[j], num);
        }
        den = warp_sum(den); num = warp_sum(num);
        if (lane == 0) g_attn[i] = (num / den) * ow + ob;
    }
}

// ---------------- gate matvec + final fuse ----------------
__global__ __launch_bounds__(256)
void final_kernel(const float* __restrict__ W, const float* __restrict__ gb,
                  const float* __restrict__ gamma, const float* __restrict__ lmbda,
                  float* __restrict__ out)
{
    int warp = threadIdx.x >> 5, lane = threadIdx.x & 31;
    int i = blockIdx.x * 8 + warp;
    const float4* Wr = (const float4*)(W + (size_t)i * Ldim);
    const float4* U4 = (const float4*)g_u;
    float acc = 0.f;
    for (int k = lane; k < Ldim/4; k += 32) {
        float4 w4 = Wr[k]; float4 u4 = U4[k];
        acc += w4.x*u4.x + w4.y*u4.y + w4.z*u4.z + w4.w*u4.w;
    }
    acc = warp_sum(acc);
    if (lane == 0) {
        float z = acc + gb[i];
        float g = 1.f / (1.f + expf(-z));
        float s = g * g_v[i] + (1.f - g) * gamma[i] + g_attn[i] - lmbda[0];
        out[i] = fmaxf(s, 0.f);
    }
}

// ---------------- launch ----------------
extern "C" void kernel_launch(void* const* d_in, const int* in_sizes, int n_in,
                              void* d_out, int out_size)
{
    const float* gamma  = (const float*)d_in[0];
    const float* A_re   = (const float*)d_in[1];
    const float* A_im   = (const float*)d_in[2];
    const float* X_re   = (const float*)d_in[3];
    const float* X_im   = (const float*)d_in[4];
    const float* ln_w   = (const float*)d_in[5];
    const float* ln_b   = (const float*)d_in[6];
    const float* in_w   = (const float*)d_in[7];
    const float* in_b   = (const float*)d_in[8];
    const float* out_w  = (const float*)d_in[9];
    const float* out_b  = (const float*)d_in[10];
    const float* gate_W = (const float*)d_in[11];
    const float* gate_b = (const float*)d_in[12];
    const float* delta  = (const float*)d_in[13];
    const float* lmbda  = (const float*)d_in[14];
    float* out = (float*)d_out;

    cudaFuncSetAttribute(cgemm_mma, cudaFuncAttributeMaxDynamicSharedMemorySize, ENG_SMEM2);

    float *Rre,*Rim,*Gre,*Gim,*Xare,*Xaim,*Xbre,*Xbim,*Pre,*Pim;
    float *pre,*pim,*Atre,*Atim,*Ztre,*Ztim,*GZre,*GZim;
    cudaGetSymbolAddress((void**)&Rre,  g_Rre);   cudaGetSymbolAddress((void**)&Rim,  g_Rim);
    cudaGetSymbolAddress((void**)&Gre,  g_Gre);   cudaGetSymbolAddress((void**)&Gim,  g_Gim);
    cudaGetSymbolAddress((void**)&Xare, g_Xa_re); cudaGetSymbolAddress((void**)&Xaim, g_Xa_im);
    cudaGetSymbolAddress((void**)&Xbre, g_Xb_re); cudaGetSymbolAddress((void**)&Xbim, g_Xb_im);
    cudaGetSymbolAddress((void**)&Pre,  g_P_re);  cudaGetSymbolAddress((void**)&Pim,  g_P_im);
    cudaGetSymbolAddress((void**)&pre,  g_part_re); cudaGetSymbolAddress((void**)&pim, g_part_im);
    cudaGetSymbolAddress((void**)&Atre, g_Atre);  cudaGetSymbolAddress((void**)&Atim, g_Atim);
    cudaGetSymbolAddress((void**)&Ztre, g_Ztre);  cudaGetSymbolAddress((void**)&Ztim, g_Ztim);
    cudaGetSymbolAddress((void**)&GZre, g_GZre);  cudaGetSymbolAddress((void**)&GZim, g_GZim);

    // At = A^T (planar)
    transposeA<<<dim3(128, 8), dim3(32, 8)>>>(A_re, A_im);

    // R (Hermitian): 6 lower/diag tiles, 16-way k-split; reduce; mirror upper-right
    csyrk_big<<<dim3(6,1,16), 256>>>(pre, pim, A_re, A_im, gamma, Ldim, 256);
    reduce_RG<<<256, 256>>>(Rre, Rim, 16, 1);
    mirror_R<<<64, 256>>>();

    // G = X X^H : 2-split conj MMA (q-chain), 16-way k-split
    cgemm_mma<<<dim3(2,2,32), 256, ENG_SMEM2>>>(X_re, X_im, Tdim, X_re, X_im, Tdim,
                                                pre, pim, Mdim, 128, 1, nullptr, 65536);
    reduce_RG<<<256, 256>>>(Gre, Gim, 16, 0);

    // alpha; X1 = 2aI - a^2 R  (free first Newton step, elementwise)
    trace_alpha<<<1, 1024>>>();
    init_X1<<<256, 256>>>(Xare, Xaim);

    // order-2 Newton (fp32): Xn = 2X - X(RX), 6 GEMM-iterations (total depth 2^7)
    // GEMM1 -> partial slots 0..15 ; GEMM2 (fused B-sum of slots 0..15) -> slots 16..31
    float *Xc_re = Xare, *Xc_im = Xaim, *Xn_re = Xbre, *Xn_im = Xbim;
    for (int it = 0; it < 6; ++it) {
        cgemm_big<<<dim3(4,2,16), 256>>>(pre, pim, Rre, Rim, Mdim,
                                         Xc_re, Xc_im, Mdim, 16, 65536);
        cgemm_fsum<<<dim3(4,2,16), 256>>>(pre + (size_t)16*65536, pim + (size_t)16*65536,
                                          Xc_re, Xc_im, Mdim,
                                          pre, pim, Mdim, 16, 16, 65536);
        reduce_newton<<<256, 256>>>(Xn_re, Xn_im, Xc_re, Xc_im, 16, 16);
        float* tmp;
        tmp = Xc_re; Xc_re = Xn_re; Xn_re = tmp;
        tmp = Xc_im; Xc_im = Xn_im; Xn_im = tmp;
    }

    // Bc = conj(symmetrized Rinv)
    symm_conj<<<256, 256>>>(Xc_re, Xc_im, Pre, Pim);

    // Zt[l,m] = sum_k At[l,k] * Bc[k,m]   (fp32, full-K)
    cgemm_big<<<dim3(4,32,1), 256>>>(Ztre, Ztim, Atre, Atim, Mdim,
                                     Pre, Pim, Mdim, 256, 0);

    // GZt[l,m] = sum_k Zt[l,k] * G[m,k]   (2-split MMA, q-chain)
    cgemm_mma<<<dim3(2,32,2), 256, ENG_SMEM2>>>(Ztre, Ztim, Mdim, Gre, Gim, Mdim,
                                                GZre, GZim, Mdim, 256, 0, nullptr, 0);

    qduv_kernel<<<512, 256>>>(gamma, delta);
    ln_kernel<<<1, 512>>>(ln_w, ln_b, in_w, in_b);
    attn_kernel<<<128, 256>>>(in_w, in_b, out_w, out_b);
    final_kernel<<<512, 256>>>(gate_W, gate_b, gamma, lmbda, out);
}